// round 12
// baseline (speedup 1.0000x reference)
#include <cuda_runtime.h>
#include <math.h>

#define NN   10000
#define EE   320000
#define DIM  176
#define ATT  16
#define SHH  16
#define THH  4
#define NHH  20
#define VD   11
#define NSPH 16
#define RDIMC 16
#define QKVW 816   // 320 + 320 + 176

typedef unsigned long long u64;
typedef long long ll;

// ---------------- scratch ----------------
__device__ float g_xi [NN * DIM];
__device__ float g_qkv[NN * QKVW];   // per node: qT[80 float4] | kT[80 float4] | v[176]
__device__ float g_mi [NN * DIM];
__device__ float g_Vi [NN * THH * NSPH];
__device__ float g_Y  [EE * NSPH];
__device__ float g_G  [NN * DIM];
__device__ float g_w  [(ll)EE * 16];   // per-edge MLP output (switch-scaled)
__device__ int   g_cnt[NN];
__device__ int   g_eid[EE];

// ---------------- helpers ----------------
__device__ __forceinline__ u64 pack2(float x, float y) {
    u64 r; asm("mov.b64 %0,{%1,%2};" : "=l"(r) : "f"(x), "f"(y)); return r;
}
__device__ __forceinline__ void fma2(u64& d, u64 a, u64 b) {
    asm("fma.rn.f32x2 %0, %1, %2, %3;" : "=l"(d) : "l"(a), "l"(b), "l"(d));
}
__device__ __forceinline__ float2 unpack2(u64 v) {
    float2 f; asm("mov.b64 {%0,%1},%2;" : "=f"(f.x), "=f"(f.y) : "l"(v)); return f;
}

__device__ __forceinline__ float block_sum_192(float v, float* red) {
    #pragma unroll
    for (int o = 16; o; o >>= 1) v += __shfl_xor_sync(0xffffffffu, v, o);
    if ((threadIdx.x & 31) == 0) red[threadIdx.x >> 5] = v;
    __syncthreads();
    float s = 0.f;
    if (threadIdx.x < 6) s = red[threadIdx.x];
    if (threadIdx.x < 32) {
        s += __shfl_xor_sync(0xffffffffu, s, 4);
        s += __shfl_xor_sync(0xffffffffu, s, 2);
        s += __shfl_xor_sync(0xffffffffu, s, 1);
        if (threadIdx.x == 0) red[0] = s;
    }
    __syncthreads();
    float r = red[0];
    __syncthreads();
    return r;
}

// radial basis in registers
__device__ __forceinline__ void radial_eval(float d, float* R) {
    const float invs = 1.f / 0.28f;
    #pragma unroll
    for (int r = 0; r < 16; r++) {
        float c = 0.8f + 0.28f * (float)r;
        float tt = (d - c) * invs;
        R[r] = __expf(-tt * tt);
    }
}

// thread-local MLP: u[UR] -> w[16], weights in smem (float4 broadcast)
template<int UR>
__device__ __forceinline__ void mlp_eval(const float* u,
                                         const float4* s_pw1, const float* s_b1,
                                         const float4* s_pw2, const float* s_b2,
                                         float* w) {
    float h[32];
    #pragma unroll
    for (int j = 0; j < 32; j++) h[j] = s_b1[j];
    #pragma unroll
    for (int r = 0; r < UR; r++) {
        float uv = u[r];
        #pragma unroll
        for (int j4 = 0; j4 < 8; j4++) {
            float4 p = s_pw1[r * 8 + j4];
            h[4*j4+0] += uv * p.x; h[4*j4+1] += uv * p.y;
            h[4*j4+2] += uv * p.z; h[4*j4+3] += uv * p.w;
        }
    }
    #pragma unroll
    for (int j = 0; j < 32; j++) h[j] = h[j] / (1.f + __expf(-h[j]));
    #pragma unroll
    for (int d = 0; d < 16; d++) w[d] = s_b2[d];
    #pragma unroll
    for (int j = 0; j < 32; j++) {
        float hv = h[j];
        #pragma unroll
        for (int d4 = 0; d4 < 4; d4++) {
            float4 p = s_pw2[j * 4 + d4];
            w[4*d4+0] += hv * p.x; w[4*d4+1] += hv * p.y;
            w[4*d4+2] += hv * p.z; w[4*d4+3] += hv * p.w;
        }
    }
}

// ---------------- node embedding (+ zero mi, Vi, cnt) ----------------
__global__ void node_embed_kernel(const int* __restrict__ species,
                                  const float* __restrict__ zt,
                                  const float* __restrict__ wsp) {
    __shared__ float sZ[16];
    __shared__ float red[8];
    int n = blockIdx.x;
    int t = threadIdx.x;
    if (t < DIM) g_mi[(ll)n * DIM + t] = 0.f;
    if (t < 64)  g_Vi[n * 64 + t] = 0.f;
    if (t == 64) g_cnt[n] = 0;
    if (t < 16) sZ[t] = zt[species[n] * 16 + t];
    __syncthreads();
    float val = 0.f;
    if (t < DIM) {
        #pragma unroll
        for (int z = 0; z < 16; z++) val += sZ[z] * wsp[z * DIM + t];
    }
    float mu = block_sum_192(val, red) * (1.f / DIM);
    float dx = (t < DIM) ? (val - mu) : 0.f;
    float var = block_sum_192(dx * dx, red) * (1.f / DIM);
    if (t < DIM) g_xi[n * DIM + t] = dx * rsqrtf(var + 1e-6f);
}

// ---------------- edge geometry + fused layer-0 MLP (+ dst histogram) ----------------
__global__ __launch_bounds__(256) void edge_geom_kernel(
    const float* __restrict__ dist, const float* __restrict__ vec,
    const float* __restrict__ swtch, const int* __restrict__ dst,
    const float* __restrict__ pw1, const float* __restrict__ pb1,
    const float* __restrict__ pw2, const float* __restrict__ pb2)
{
    __shared__ float4 s_pw1[128];   // 16x32
    __shared__ float4 s_pw2[128];   // 32x16
    __shared__ float  s_b1[32];
    __shared__ float  s_b2[16];
    int tid = threadIdx.x;
    for (int i = tid; i < 128; i += 256) {
        s_pw1[i] = reinterpret_cast<const float4*>(pw1)[i];
        s_pw2[i] = reinterpret_cast<const float4*>(pw2)[i];
    }
    if (tid < 32) s_b1[tid] = pb1[tid];
    if (tid < 16) s_b2[tid] = pb2[tid];
    __syncthreads();

    int e = blockIdx.x * blockDim.x + tid;
    if (e >= EE) return;
    atomicAdd(&g_cnt[dst[e]], 1);
    float d = dist[e];
    float inv = 1.f / d;
    float x = vec[e * 3 + 0] * inv;
    float y = vec[e * 3 + 1] * inv;
    float z = vec[e * 3 + 2] * inv;
    const float s3  = 1.7320508075688772f;
    const float s15 = 3.872983346207417f;
    const float c1  = 0.7905694150420949f;
    const float c2  = 0.6123724356957945f;
    float x2 = x * x, y2 = y * y, z2 = z * z;
    float Y[16];
    Y[0]  = 1.f;
    Y[1]  = x; Y[2] = y; Y[3] = z;
    Y[4]  = s3 * x * y;
    Y[5]  = s3 * y * z;
    Y[6]  = 0.5f * (3.f * z2 - 1.f);
    Y[7]  = s3 * x * z;
    Y[8]  = 0.5f * s3 * (x2 - y2);
    Y[9]  = c1 * y * (3.f * x2 - y2);
    Y[10] = s15 * x * y * z;
    Y[11] = c2 * y * (5.f * z2 - 1.f);
    Y[12] = 0.5f * z * (5.f * z2 - 3.f);
    Y[13] = c2 * x * (5.f * z2 - 1.f);
    Y[14] = 0.5f * s15 * z * (x2 - y2);
    Y[15] = c1 * x * (x2 - 3.f * y2);
    float R[16];
    radial_eval(d, R);
    float4* yo = reinterpret_cast<float4*>(g_Y + e * 16);
    #pragma unroll
    for (int i = 0; i < 4; i++)
        yo[i] = make_float4(Y[4*i], Y[4*i+1], Y[4*i+2], Y[4*i+3]);
    float w[16];
    mlp_eval<16>(R, s_pw1, s_b1, s_pw2, s_b2, w);
    float sws = swtch[e] * 0.25f;
    float4* wp = reinterpret_cast<float4*>(g_w + (ll)e * 16);
    #pragma unroll
    for (int d4 = 0; d4 < 4; d4++)
        wp[d4] = make_float4(w[4*d4] * sws, w[4*d4+1] * sws, w[4*d4+2] * sws, w[4*d4+3] * sws);
}

// ---------------- CSR scan (exclusive prefix into g_cnt) + scatter ----------------
__global__ __launch_bounds__(1024) void csr_scan_kernel() {
    __shared__ int s_warp[32];
    int tid = threadIdx.x;
    int lane = tid & 31, w = tid >> 5;
    int run = 0;
    for (int chunk = 0; chunk < NN; chunk += 1024) {
        int i = chunk + tid;
        int val = (i < NN) ? g_cnt[i] : 0;
        int v = val;
        #pragma unroll
        for (int o = 1; o < 32; o <<= 1) {
            int n = __shfl_up_sync(0xffffffffu, v, o);
            if (lane >= o) v += n;
        }
        if (lane == 31) s_warp[w] = v;
        __syncthreads();
        if (w == 0) {
            int x = s_warp[lane];
            #pragma unroll
            for (int o = 1; o < 32; o <<= 1) {
                int n = __shfl_up_sync(0xffffffffu, x, o);
                if (lane >= o) x += n;
            }
            s_warp[lane] = x;
        }
        __syncthreads();
        int incl = v + (w > 0 ? s_warp[w - 1] : 0);
        int excl = incl - val + run;
        if (i < NN) g_cnt[i] = excl;
        run += s_warp[31];
        __syncthreads();
    }
}
__global__ void csr_scatter_kernel(const int* __restrict__ dst) {
    int e = blockIdx.x * blockDim.x + threadIdx.x;
    if (e < EE) {
        int pos = atomicAdd(&g_cnt[dst[e]], 1);
        g_eid[pos] = e;
    }
}

// ---------------- fused layer-1 ur gather + MLP (parallel phase A) ----------------
#define U2PAD 264
__global__ __launch_bounds__(256) void ur1mlp1_kernel(
    const int* __restrict__ src, const int* __restrict__ dst,
    const float* __restrict__ dist, const float* __restrict__ swtch,
    const float* __restrict__ pw1, const float* __restrict__ pb1,
    const float* __restrict__ pw2, const float* __restrict__ pb2)
{
    __shared__ float4 s_pw1[256];   // 32x32
    __shared__ float4 s_pw2[128];   // 32x16
    __shared__ float  s_b1[32];
    __shared__ float  s_b2[16];
    __shared__ float  s_u2[16][U2PAD];

    int tid = threadIdx.x;
    for (int i = tid; i < 256; i += 256) s_pw1[i] = reinterpret_cast<const float4*>(pw1)[i];
    for (int i = tid; i < 128; i += 256) s_pw2[i] = reinterpret_cast<const float4*>(pw2)[i];
    if (tid < 32) s_b1[tid] = pb1[tid];
    if (tid < 16) s_b2[tid] = pb2[tid];
    __syncthreads();

    int wid = tid >> 5, lane = tid & 31;
    int base = blockIdx.x * 256;
    int tap = lane & 3;
    int eo  = lane >> 2;   // 0..7

    #pragma unroll
    for (int it = 0; it < 4; it++) {
        int e_loc = wid * 32 + it * 8 + eo;
        int e = base + e_loc;
        if (e < EE) {
            int is = src[e], id = dst[e];
            const float4* Yp = reinterpret_cast<const float4*>(g_Y + e * 16);
            float Yv[16];
            #pragma unroll
            for (int q = 0; q < 4; q++) {
                float4 y4 = Yp[q];
                Yv[4*q]=y4.x; Yv[4*q+1]=y4.y; Yv[4*q+2]=y4.z; Yv[4*q+3]=y4.w;
            }
            const float4* Vd4 = reinterpret_cast<const float4*>(&g_Vi[(ll)id * 64 + tap * 16]);
            const float4* Vs4 = reinterpret_cast<const float4*>(&g_Vi[(ll)is * 64 + tap * 16]);
            float Vd[16], Vs[16];
            #pragma unroll
            for (int q = 0; q < 4; q++) {
                float4 a4 = Vd4[q], b4 = Vs4[q];
                Vd[4*q]=a4.x; Vd[4*q+1]=a4.y; Vd[4*q+2]=a4.z; Vd[4*q+3]=a4.w;
                Vs[4*q]=b4.x; Vs[4*q+1]=b4.y; Vs[4*q+2]=b4.z; Vs[4*q+3]=b4.w;
            }
            float u0 = (Vd[0] + Vs[0]) * Yv[0];
            float u1 = 0.f, u2 = 0.f, u3 = 0.f;
            #pragma unroll
            for (int m = 1; m < 4; m++)  u1 += (Vd[m] - Vs[m]) * Yv[m];
            #pragma unroll
            for (int m = 4; m < 9; m++)  u2 += (Vd[m] + Vs[m]) * Yv[m];
            #pragma unroll
            for (int m = 9; m < 16; m++) u3 += (Vd[m] - Vs[m]) * Yv[m];
            s_u2[ 0 + tap][e_loc] = u0;
            s_u2[ 4 + tap][e_loc] = u1;
            s_u2[ 8 + tap][e_loc] = u2;
            s_u2[12 + tap][e_loc] = u3;
        }
    }
    __syncthreads();

    int e = base + tid;
    if (e >= EE) return;
    float u[32];
    radial_eval(dist[e], u);
    #pragma unroll
    for (int j = 0; j < 16; j++) u[16 + j] = s_u2[j][tid];
    float w[16];
    mlp_eval<32>(u, s_pw1, s_b1, s_pw2, s_b2, w);
    float sws = swtch[e] * 0.25f;
    float4* wp = reinterpret_cast<float4*>(g_w + (ll)e * 16);
    #pragma unroll
    for (int d4 = 0; d4 < 4; d4++)
        wp[d4] = make_float4(w[4*d4] * sws, w[4*d4+1] * sws, w[4*d4+2] * sws, w[4*d4+3] * sws);
}

// ---------------- QKV SGEMM (double-buffered, head-transposed q/k out) ----------------
__global__ __launch_bounds__(256, 2) void sgemm_qkv_kernel(
    const float* __restrict__ wq, const float* __restrict__ wk,
    const float* __restrict__ wv)
{
    __shared__ u64   As2[2][16][128];
    __shared__ float Bs [2][16][128];
    int tid = threadIdx.x;
    int tx = tid & 15, ty = tid >> 4;
    int row0 = blockIdx.y * 128;
    int col0 = blockIdx.x * 128;
    u64 acc[8][4];
    #pragma unroll
    for (int i = 0; i < 8; i++)
        #pragma unroll
        for (int j = 0; j < 4; j++) acc[i][j] = 0ull;

    const int ar = tid >> 1;
    const int ac0 = (tid & 1) * 8;
    const int agrow = row0 + ar;
    const int bbr = tid >> 4;
    const int bbc = (tid & 15) * 8;
    const int bgcol = col0 + bbc;

    float4 pa0, pa1, pb0, pb1;
    {
        pa0 = make_float4(0,0,0,0); pa1 = make_float4(0,0,0,0);
        if (agrow < NN) {
            const float* s = g_xi + (ll)agrow * DIM + ac0;
            pa0 = *reinterpret_cast<const float4*>(s);
            pa1 = *reinterpret_cast<const float4*>(s + 4);
        }
        pb0 = make_float4(0,0,0,0); pb1 = make_float4(0,0,0,0);
        if (bgcol < QKVW) {
            const float* srcp; int c;
            if (bgcol < 320)      { srcp = wq + (ll)bbr * 320; c = bgcol; }
            else if (bgcol < 640) { srcp = wk + (ll)bbr * 320; c = bgcol - 320; }
            else                  { srcp = wv + (ll)bbr * 176; c = bgcol - 640; }
            pb0 = *reinterpret_cast<const float4*>(srcp + c);
            pb1 = *reinterpret_cast<const float4*>(srcp + c + 4);
        }
        As2[0][ac0+0][ar] = pack2(pa0.x, pa0.x);
        As2[0][ac0+1][ar] = pack2(pa0.y, pa0.y);
        As2[0][ac0+2][ar] = pack2(pa0.z, pa0.z);
        As2[0][ac0+3][ar] = pack2(pa0.w, pa0.w);
        As2[0][ac0+4][ar] = pack2(pa1.x, pa1.x);
        As2[0][ac0+5][ar] = pack2(pa1.y, pa1.y);
        As2[0][ac0+6][ar] = pack2(pa1.z, pa1.z);
        As2[0][ac0+7][ar] = pack2(pa1.w, pa1.w);
        *reinterpret_cast<float4*>(&Bs[0][bbr][bbc])     = pb0;
        *reinterpret_cast<float4*>(&Bs[0][bbr][bbc + 4]) = pb1;
    }
    __syncthreads();

    for (int kt = 0; kt < 11; ++kt) {
        int cur = kt & 1, nxt = cur ^ 1;
        bool has_nxt = (kt + 1 < 11);
        if (has_nxt) {
            int gkbase = (kt + 1) * 16;
            pa0 = make_float4(0,0,0,0); pa1 = make_float4(0,0,0,0);
            if (agrow < NN) {
                const float* s = g_xi + (ll)agrow * DIM + gkbase + ac0;
                pa0 = *reinterpret_cast<const float4*>(s);
                pa1 = *reinterpret_cast<const float4*>(s + 4);
            }
            int gk = gkbase + bbr;
            pb0 = make_float4(0,0,0,0); pb1 = make_float4(0,0,0,0);
            if (bgcol < QKVW) {
                const float* srcp; int c;
                if (bgcol < 320)      { srcp = wq + (ll)gk * 320; c = bgcol; }
                else if (bgcol < 640) { srcp = wk + (ll)gk * 320; c = bgcol - 320; }
                else                  { srcp = wv + (ll)gk * 176; c = bgcol - 640; }
                pb0 = *reinterpret_cast<const float4*>(srcp + c);
                pb1 = *reinterpret_cast<const float4*>(srcp + c + 4);
            }
        }
        #pragma unroll
        for (int k = 0; k < 16; ++k) {
            u64 a[8];
            {
                const ulonglong2* p = reinterpret_cast<const ulonglong2*>(&As2[cur][k][ty * 8]);
                ulonglong2 q0 = p[0], q1 = p[1], q2 = p[2], q3 = p[3];
                a[0]=q0.x; a[1]=q0.y; a[2]=q1.x; a[3]=q1.y;
                a[4]=q2.x; a[5]=q2.y; a[6]=q3.x; a[7]=q3.y;
            }
            u64 b[4];
            {
                const ulonglong2* p = reinterpret_cast<const ulonglong2*>(&Bs[cur][k][tx * 8]);
                ulonglong2 w0 = p[0], w1 = p[1];
                b[0]=w0.x; b[1]=w0.y; b[2]=w1.x; b[3]=w1.y;
            }
            #pragma unroll
            for (int i = 0; i < 8; i++)
                #pragma unroll
                for (int j = 0; j < 4; j++)
                    fma2(acc[i][j], a[i], b[j]);
        }
        if (has_nxt) {
            As2[nxt][ac0+0][ar] = pack2(pa0.x, pa0.x);
            As2[nxt][ac0+1][ar] = pack2(pa0.y, pa0.y);
            As2[nxt][ac0+2][ar] = pack2(pa0.z, pa0.z);
            As2[nxt][ac0+3][ar] = pack2(pa0.w, pa0.w);
            As2[nxt][ac0+4][ar] = pack2(pa1.x, pa1.x);
            As2[nxt][ac0+5][ar] = pack2(pa1.y, pa1.y);
            As2[nxt][ac0+6][ar] = pack2(pa1.z, pa1.z);
            As2[nxt][ac0+7][ar] = pack2(pa1.w, pa1.w);
            *reinterpret_cast<float4*>(&Bs[nxt][bbr][bbc])     = pb0;
            *reinterpret_cast<float4*>(&Bs[nxt][bbr][bbc + 4]) = pb1;
            __syncthreads();
        }
    }
    #pragma unroll
    for (int i = 0; i < 8; i++) {
        int gr = row0 + ty * 8 + i;
        if (gr >= NN) continue;
        #pragma unroll
        for (int j = 0; j < 4; j++) {
            int gc = col0 + tx * 8 + j * 2;
            if (gc < QKVW) {
                float2 f = unpack2(acc[i][j]);
                int oc;
                if (gc < 640) {
                    int blk = (gc < 320) ? 0 : 320;
                    int c = gc - blk;
                    int h = c >> 4, d = c & 15;
                    oc = blk + ((d >> 2) * 20 + h) * 4 + (d & 3);
                } else {
                    oc = gc;
                }
                *reinterpret_cast<float2*>(&g_qkv[(ll)gr * QKVW + oc]) = f;
            }
        }
    }
}

// ---------------- update SGEMM (double-buffered): G = [xi|mi] @ uw ----------------
__global__ __launch_bounds__(256, 2) void sgemm_upd_kernel(const float* __restrict__ B)
{
    __shared__ u64   As2[2][16][128];
    __shared__ float Bs [2][16][128];
    int tid = threadIdx.x;
    int tx = tid & 15, ty = tid >> 4;
    int row0 = blockIdx.y * 128;
    int col0 = blockIdx.x * 128;
    u64 acc[8][4];
    #pragma unroll
    for (int i = 0; i < 8; i++)
        #pragma unroll
        for (int j = 0; j < 4; j++) acc[i][j] = 0ull;

    const int ar = tid >> 1;
    const int ac0 = (tid & 1) * 8;
    const int agrow = row0 + ar;
    const int bbr = tid >> 4;
    const int bbc = (tid & 15) * 8;
    const int bgcol = col0 + bbc;

    float4 pa0, pa1, pb0, pb1;
    {
        pa0 = make_float4(0,0,0,0); pa1 = make_float4(0,0,0,0);
        if (agrow < NN) {
            const float* s = g_xi + (ll)agrow * DIM + ac0;
            pa0 = *reinterpret_cast<const float4*>(s);
            pa1 = *reinterpret_cast<const float4*>(s + 4);
        }
        pb0 = make_float4(0,0,0,0); pb1 = make_float4(0,0,0,0);
        if (bgcol < DIM) {
            const float* s = B + (ll)bbr * DIM + bgcol;
            pb0 = *reinterpret_cast<const float4*>(s);
            pb1 = *reinterpret_cast<const float4*>(s + 4);
        }
        As2[0][ac0+0][ar] = pack2(pa0.x, pa0.x);
        As2[0][ac0+1][ar] = pack2(pa0.y, pa0.y);
        As2[0][ac0+2][ar] = pack2(pa0.z, pa0.z);
        As2[0][ac0+3][ar] = pack2(pa0.w, pa0.w);
        As2[0][ac0+4][ar] = pack2(pa1.x, pa1.x);
        As2[0][ac0+5][ar] = pack2(pa1.y, pa1.y);
        As2[0][ac0+6][ar] = pack2(pa1.z, pa1.z);
        As2[0][ac0+7][ar] = pack2(pa1.w, pa1.w);
        *reinterpret_cast<float4*>(&Bs[0][bbr][bbc])     = pb0;
        *reinterpret_cast<float4*>(&Bs[0][bbr][bbc + 4]) = pb1;
    }
    __syncthreads();

    for (int kt = 0; kt < 22; ++kt) {
        int cur = kt & 1, nxt = cur ^ 1;
        bool has_nxt = (kt + 1 < 22);
        if (has_nxt) {
            int gkbase = (kt + 1) * 16;
            const float* Ap = (gkbase < DIM) ? g_xi : g_mi;
            int koff = (gkbase < DIM) ? gkbase : gkbase - DIM;
            pa0 = make_float4(0,0,0,0); pa1 = make_float4(0,0,0,0);
            if (agrow < NN) {
                const float* s = Ap + (ll)agrow * DIM + koff + ac0;
                pa0 = *reinterpret_cast<const float4*>(s);
                pa1 = *reinterpret_cast<const float4*>(s + 4);
            }
            int gk = gkbase + bbr;
            pb0 = make_float4(0,0,0,0); pb1 = make_float4(0,0,0,0);
            if (bgcol < DIM) {
                const float* s = B + (ll)gk * DIM + bgcol;
                pb0 = *reinterpret_cast<const float4*>(s);
                pb1 = *reinterpret_cast<const float4*>(s + 4);
            }
        }
        #pragma unroll
        for (int k = 0; k < 16; ++k) {
            u64 a[8];
            {
                const ulonglong2* p = reinterpret_cast<const ulonglong2*>(&As2[cur][k][ty * 8]);
                ulonglong2 q0 = p[0], q1 = p[1], q2 = p[2], q3 = p[3];
                a[0]=q0.x; a[1]=q0.y; a[2]=q1.x; a[3]=q1.y;
                a[4]=q2.x; a[5]=q2.y; a[6]=q3.x; a[7]=q3.y;
            }
            u64 b[4];
            {
                const ulonglong2* p = reinterpret_cast<const ulonglong2*>(&Bs[cur][k][tx * 8]);
                ulonglong2 w0 = p[0], w1 = p[1];
                b[0]=w0.x; b[1]=w0.y; b[2]=w1.x; b[3]=w1.y;
            }
            #pragma unroll
            for (int i = 0; i < 8; i++)
                #pragma unroll
                for (int j = 0; j < 4; j++)
                    fma2(acc[i][j], a[i], b[j]);
        }
        if (has_nxt) {
            As2[nxt][ac0+0][ar] = pack2(pa0.x, pa0.x);
            As2[nxt][ac0+1][ar] = pack2(pa0.y, pa0.y);
            As2[nxt][ac0+2][ar] = pack2(pa0.z, pa0.z);
            As2[nxt][ac0+3][ar] = pack2(pa0.w, pa0.w);
            As2[nxt][ac0+4][ar] = pack2(pa1.x, pa1.x);
            As2[nxt][ac0+5][ar] = pack2(pa1.y, pa1.y);
            As2[nxt][ac0+6][ar] = pack2(pa1.z, pa1.z);
            As2[nxt][ac0+7][ar] = pack2(pa1.w, pa1.w);
            *reinterpret_cast<float4*>(&Bs[nxt][bbr][bbc])     = pb0;
            *reinterpret_cast<float4*>(&Bs[nxt][bbr][bbc + 4]) = pb1;
            __syncthreads();
        }
    }
    #pragma unroll
    for (int i = 0; i < 8; i++) {
        int gr = row0 + ty * 8 + i;
        if (gr >= NN) continue;
        #pragma unroll
        for (int j = 0; j < 4; j++) {
            int gc = col0 + tx * 8 + j * 2;
            if (gc < DIM) {
                float2 f = unpack2(acc[i][j]);
                *reinterpret_cast<float2*>(&g_G[(ll)gr * DIM + gc]) = f;
            }
        }
    }
}

// ---------------- slim edge attention + scatter (dst-sorted order) ----------------
template<int LAYER>
__global__ __launch_bounds__(256) void edge_attn_kernel(
    const int* __restrict__ src, const int* __restrict__ dst)
{
    __shared__ float s_a[8][20];

    int tid = threadIdx.x;
    int wid = tid >> 5, lane = tid & 31;
    int b0a = 4 * lane;
    int b0b = 4 * (lane + 32);
    int hA0 =  b0a      / VD, hA1 = (b0a + 1) / VD, hA2 = (b0a + 2) / VD, hA3 = (b0a + 3) / VD;
    int hB0 =  b0b      / VD, hB1 = (b0b + 1) / VD, hB2 = (b0b + 2) / VD, hB3 = (b0b + 3) / VD;

    for (int t = blockIdx.x * 8 + wid; t < EE; t += gridDim.x * 8) {
        int e = __ldg(&g_eid[t]);
        int is = src[e], id = dst[e];
        float4 y4;
        if (LAYER == 0 && lane < 16)
            y4 = __ldg(reinterpret_cast<const float4*>(g_Y) + e * 4 + (lane & 3));
        const float4* qT = reinterpret_cast<const float4*>(g_qkv + (ll)id * QKVW);
        const float4* kT = reinterpret_cast<const float4*>(g_qkv + (ll)is * QKVW + 320);
        const float4* wp = reinterpret_cast<const float4*>(g_w + (ll)e * 16);
        if (lane < 20) {
            float a0 = 0.f, a1 = 0.f;
            #pragma unroll
            for (int d4 = 0; d4 < 4; d4++) {
                float4 q4 = qT[d4 * 20 + lane];
                float4 k4 = kT[d4 * 20 + lane];
                float4 w4 = __ldg(wp + d4);
                a0 += q4.x * k4.x * w4.x + q4.y * k4.y * w4.y;
                a1 += q4.z * k4.z * w4.z + q4.w * k4.w * w4.w;
            }
            s_a[wid][lane] = a0 + a1;
        }
        __syncwarp();
        const float* vr = g_qkv + (ll)is * QKVW + 640;
        float* mr = &g_mi[(ll)id * DIM];
        {
            float4 v4 = *reinterpret_cast<const float4*>(vr + b0a);
            float4 o;
            o.x = s_a[wid][hA0] * v4.x;
            o.y = s_a[wid][hA1] * v4.y;
            o.z = s_a[wid][hA2] * v4.z;
            o.w = s_a[wid][hA3] * v4.w;
            atomicAdd(reinterpret_cast<float4*>(mr + b0a), o);
        }
        if (lane < 12) {
            float4 v4 = *reinterpret_cast<const float4*>(vr + b0b);
            float4 o;
            o.x = s_a[wid][hB0] * v4.x;
            o.y = s_a[wid][hB1] * v4.y;
            o.z = s_a[wid][hB2] * v4.z;
            o.w = s_a[wid][hB3] * v4.w;
            atomicAdd(reinterpret_cast<float4*>(mr + b0b), o);
        }
        if (LAYER == 0) {
            if (lane < 16) {
                float at = s_a[wid][16 + (lane >> 2)];
                float4 o = make_float4(at * y4.x, at * y4.y, at * y4.z, at * y4.w);
                atomicAdd(reinterpret_cast<float4*>(&g_Vi[(ll)id * 64 + 4 * lane]), o);
            }
        }
        __syncwarp();
    }
}

// ---------------- residual + LayerNorm (+ zero mi for next layer) ----------------
__global__ void resln_kernel(const float* __restrict__ ub, float* __restrict__ out, int toXi) {
    __shared__ float red[8];
    int n = blockIdx.x, t = threadIdx.x;
    float val = 0.f;
    if (t < DIM) val = g_xi[n * DIM + t] + g_G[n * DIM + t] + ub[t];
    float mu = block_sum_192(val, red) * (1.f / DIM);
    float dx = (t < DIM) ? (val - mu) : 0.f;
    float var = block_sum_192(dx * dx, red) * (1.f / DIM);
    if (t < DIM) {
        float o = dx * rsqrtf(var + 1e-6f);
        if (toXi) {
            g_xi[n * DIM + t] = o;
            g_mi[(ll)n * DIM + t] = 0.f;
        } else {
            out[n * DIM + t] = o;
        }
    }
}

// ---------------- launch ----------------
extern "C" void kernel_launch(void* const* d_in, const int* in_sizes, int n_in,
                              void* d_out, int out_size) {
    const int*   species  = (const int*)  d_in[0];
    const float* dist     = (const float*)d_in[1];
    const float* swtch    = (const float*)d_in[2];
    const int*   esrc     = (const int*)  d_in[3];
    const int*   edst     = (const int*)  d_in[4];
    const float* vec      = (const float*)d_in[5];
    const float* z_table  = (const float*)d_in[6];
    const float* w_sp     = (const float*)d_in[7];
    const float* pw1_0    = (const float*)d_in[8];
    const float* pb1_0    = (const float*)d_in[9];
    const float* pw2_0    = (const float*)d_in[10];
    const float* pb2_0    = (const float*)d_in[11];
    const float* wq_0     = (const float*)d_in[12];
    const float* wk_0     = (const float*)d_in[13];
    const float* wv_0     = (const float*)d_in[14];
    const float* uw_0     = (const float*)d_in[15];
    const float* ub_0     = (const float*)d_in[16];
    const float* pw1_1    = (const float*)d_in[17];
    const float* pb1_1    = (const float*)d_in[18];
    const float* pw2_1    = (const float*)d_in[19];
    const float* pb2_1    = (const float*)d_in[20];
    const float* wq_1     = (const float*)d_in[21];
    const float* wk_1     = (const float*)d_in[22];
    const float* wv_1     = (const float*)d_in[23];
    const float* uw_1     = (const float*)d_in[24];
    const float* ub_1     = (const float*)d_in[25];
    float* out = (float*)d_out;

    const int EB  = (EE + 255) / 256;
    const int EWB = 1184;
    dim3 grid_qkv(7, 79);
    dim3 grid_upd(2, 79);

    node_embed_kernel<<<NN, 192>>>(species, z_table, w_sp);                              // 0 (+zero cnt)
    edge_geom_kernel<<<EB, 256>>>(dist, vec, swtch, edst, pw1_0, pb1_0, pw2_0, pb2_0);   // 1 (+count)
    csr_scan_kernel<<<1, 1024>>>();                                                      // 2
    sgemm_qkv_kernel<<<grid_qkv, 256>>>(wq_0, wk_0, wv_0);                               // 3 (profiled)
    csr_scatter_kernel<<<EB, 256>>>(edst);                                               // 4

    // ---- layer 0 ----
    edge_attn_kernel<0><<<EWB, 256>>>(esrc, edst);                                       // 5
    sgemm_upd_kernel<<<grid_upd, 256>>>(uw_0);                                           // 6
    resln_kernel<<<NN, 192>>>(ub_0, out, 1);                                             // 7

    // ---- layer 1 ----
    ur1mlp1_kernel<<<EB, 256>>>(esrc, edst, dist, swtch, pw1_1, pb1_1, pw2_1, pb2_1);    // 8
    sgemm_qkv_kernel<<<grid_qkv, 256>>>(wq_1, wk_1, wv_1);                               // 9
    edge_attn_kernel<1><<<EWB, 256>>>(esrc, edst);                                       // 10
    sgemm_upd_kernel<<<grid_upd, 256>>>(uw_1);                                           // 11
    resln_kernel<<<NN, 192>>>(ub_1, out, 0);                                             // 12
}

// round 13
// speedup vs baseline: 1.1056x; 1.1056x over previous
#include <cuda_runtime.h>
#include <math.h>

#define NN   10000
#define EE   320000
#define DIM  176
#define ATT  16
#define SHH  16
#define THH  4
#define NHH  20
#define VD   11
#define NSPH 16
#define RDIMC 16
#define QKVW 816   // 320 + 320 + 176

typedef unsigned long long u64;
typedef long long ll;

// ---------------- scratch ----------------
__device__ float g_xi [NN * DIM];
__device__ float g_qkv[NN * QKVW];   // per node: qT[80 float4] | kT[80 float4] | v[176]
__device__ float g_mi [NN * DIM];
__device__ float g_Vi [NN * THH * NSPH];
__device__ float g_Y  [EE * NSPH];
__device__ float g_G  [NN * DIM];
__device__ float g_w  [(ll)EE * 16];   // per-edge MLP output (switch-scaled)

// ---------------- helpers ----------------
__device__ __forceinline__ u64 pack2(float x, float y) {
    u64 r; asm("mov.b64 %0,{%1,%2};" : "=l"(r) : "f"(x), "f"(y)); return r;
}
__device__ __forceinline__ void fma2(u64& d, u64 a, u64 b) {
    asm("fma.rn.f32x2 %0, %1, %2, %3;" : "=l"(d) : "l"(a), "l"(b), "l"(d));
}
__device__ __forceinline__ float2 unpack2(u64 v) {
    float2 f; asm("mov.b64 {%0,%1},%2;" : "=f"(f.x), "=f"(f.y) : "l"(v)); return f;
}

__device__ __forceinline__ float block_sum_192(float v, float* red) {
    #pragma unroll
    for (int o = 16; o; o >>= 1) v += __shfl_xor_sync(0xffffffffu, v, o);
    if ((threadIdx.x & 31) == 0) red[threadIdx.x >> 5] = v;
    __syncthreads();
    float s = 0.f;
    if (threadIdx.x < 6) s = red[threadIdx.x];
    if (threadIdx.x < 32) {
        s += __shfl_xor_sync(0xffffffffu, s, 4);
        s += __shfl_xor_sync(0xffffffffu, s, 2);
        s += __shfl_xor_sync(0xffffffffu, s, 1);
        if (threadIdx.x == 0) red[0] = s;
    }
    __syncthreads();
    float r = red[0];
    __syncthreads();
    return r;
}

// radial basis in registers
__device__ __forceinline__ void radial_eval(float d, float* R) {
    const float invs = 1.f / 0.28f;
    #pragma unroll
    for (int r = 0; r < 16; r++) {
        float c = 0.8f + 0.28f * (float)r;
        float tt = (d - c) * invs;
        R[r] = __expf(-tt * tt);
    }
}

// thread-local MLP: u[UR] -> w[16], weights in smem (float4 broadcast)
template<int UR>
__device__ __forceinline__ void mlp_eval(const float* u,
                                         const float4* s_pw1, const float* s_b1,
                                         const float4* s_pw2, const float* s_b2,
                                         float* w) {
    float h[32];
    #pragma unroll
    for (int j = 0; j < 32; j++) h[j] = s_b1[j];
    #pragma unroll
    for (int r = 0; r < UR; r++) {
        float uv = u[r];
        #pragma unroll
        for (int j4 = 0; j4 < 8; j4++) {
            float4 p = s_pw1[r * 8 + j4];
            h[4*j4+0] += uv * p.x; h[4*j4+1] += uv * p.y;
            h[4*j4+2] += uv * p.z; h[4*j4+3] += uv * p.w;
        }
    }
    #pragma unroll
    for (int j = 0; j < 32; j++) h[j] = h[j] / (1.f + __expf(-h[j]));
    #pragma unroll
    for (int d = 0; d < 16; d++) w[d] = s_b2[d];
    #pragma unroll
    for (int j = 0; j < 32; j++) {
        float hv = h[j];
        #pragma unroll
        for (int d4 = 0; d4 < 4; d4++) {
            float4 p = s_pw2[j * 4 + d4];
            w[4*d4+0] += hv * p.x; w[4*d4+1] += hv * p.y;
            w[4*d4+2] += hv * p.z; w[4*d4+3] += hv * p.w;
        }
    }
}

// ---------------- node embedding (+ zero mi, Vi for layer 0) ----------------
__global__ void node_embed_kernel(const int* __restrict__ species,
                                  const float* __restrict__ zt,
                                  const float* __restrict__ wsp) {
    __shared__ float sZ[16];
    __shared__ float red[8];
    int n = blockIdx.x;
    int t = threadIdx.x;
    if (t < DIM) g_mi[(ll)n * DIM + t] = 0.f;
    if (t < 64)  g_Vi[n * 64 + t] = 0.f;
    if (t < 16) sZ[t] = zt[species[n] * 16 + t];
    __syncthreads();
    float val = 0.f;
    if (t < DIM) {
        #pragma unroll
        for (int z = 0; z < 16; z++) val += sZ[z] * wsp[z * DIM + t];
    }
    float mu = block_sum_192(val, red) * (1.f / DIM);
    float dx = (t < DIM) ? (val - mu) : 0.f;
    float var = block_sum_192(dx * dx, red) * (1.f / DIM);
    if (t < DIM) g_xi[n * DIM + t] = dx * rsqrtf(var + 1e-6f);
}

// ---------------- edge geometry + fused layer-0 MLP (switch folded) ----------------
__global__ __launch_bounds__(256) void edge_geom_kernel(
    const float* __restrict__ dist, const float* __restrict__ vec,
    const float* __restrict__ swtch,
    const float* __restrict__ pw1, const float* __restrict__ pb1,
    const float* __restrict__ pw2, const float* __restrict__ pb2)
{
    __shared__ float4 s_pw1[128];   // 16x32
    __shared__ float4 s_pw2[128];   // 32x16
    __shared__ float  s_b1[32];
    __shared__ float  s_b2[16];
    int tid = threadIdx.x;
    for (int i = tid; i < 128; i += 256) {
        s_pw1[i] = reinterpret_cast<const float4*>(pw1)[i];
        s_pw2[i] = reinterpret_cast<const float4*>(pw2)[i];
    }
    if (tid < 32) s_b1[tid] = pb1[tid];
    if (tid < 16) s_b2[tid] = pb2[tid];
    __syncthreads();

    int e = blockIdx.x * blockDim.x + tid;
    if (e >= EE) return;
    float d = dist[e];
    float inv = 1.f / d;
    float x = vec[e * 3 + 0] * inv;
    float y = vec[e * 3 + 1] * inv;
    float z = vec[e * 3 + 2] * inv;
    const float s3  = 1.7320508075688772f;
    const float s15 = 3.872983346207417f;
    const float c1  = 0.7905694150420949f;
    const float c2  = 0.6123724356957945f;
    float x2 = x * x, y2 = y * y, z2 = z * z;
    float Y[16];
    Y[0]  = 1.f;
    Y[1]  = x; Y[2] = y; Y[3] = z;
    Y[4]  = s3 * x * y;
    Y[5]  = s3 * y * z;
    Y[6]  = 0.5f * (3.f * z2 - 1.f);
    Y[7]  = s3 * x * z;
    Y[8]  = 0.5f * s3 * (x2 - y2);
    Y[9]  = c1 * y * (3.f * x2 - y2);
    Y[10] = s15 * x * y * z;
    Y[11] = c2 * y * (5.f * z2 - 1.f);
    Y[12] = 0.5f * z * (5.f * z2 - 3.f);
    Y[13] = c2 * x * (5.f * z2 - 1.f);
    Y[14] = 0.5f * s15 * z * (x2 - y2);
    Y[15] = c1 * x * (x2 - 3.f * y2);
    float R[16];
    radial_eval(d, R);
    float4* yo = reinterpret_cast<float4*>(g_Y + e * 16);
    #pragma unroll
    for (int i = 0; i < 4; i++)
        yo[i] = make_float4(Y[4*i], Y[4*i+1], Y[4*i+2], Y[4*i+3]);
    float w[16];
    mlp_eval<16>(R, s_pw1, s_b1, s_pw2, s_b2, w);
    float sws = swtch[e] * 0.25f;
    float4* wp = reinterpret_cast<float4*>(g_w + (ll)e * 16);
    #pragma unroll
    for (int d4 = 0; d4 < 4; d4++)
        wp[d4] = make_float4(w[4*d4] * sws, w[4*d4+1] * sws, w[4*d4+2] * sws, w[4*d4+3] * sws);
}

// ---------------- fused layer-1 ur gather + MLP (parallel phase A) ----------------
#define U2PAD 264
__global__ __launch_bounds__(256) void ur1mlp1_kernel(
    const int* __restrict__ src, const int* __restrict__ dst,
    const float* __restrict__ dist, const float* __restrict__ swtch,
    const float* __restrict__ pw1, const float* __restrict__ pb1,
    const float* __restrict__ pw2, const float* __restrict__ pb2)
{
    __shared__ float4 s_pw1[256];   // 32x32
    __shared__ float4 s_pw2[128];   // 32x16
    __shared__ float  s_b1[32];
    __shared__ float  s_b2[16];
    __shared__ float  s_u2[16][U2PAD];

    int tid = threadIdx.x;
    for (int i = tid; i < 256; i += 256) s_pw1[i] = reinterpret_cast<const float4*>(pw1)[i];
    for (int i = tid; i < 128; i += 256) s_pw2[i] = reinterpret_cast<const float4*>(pw2)[i];
    if (tid < 32) s_b1[tid] = pb1[tid];
    if (tid < 16) s_b2[tid] = pb2[tid];
    __syncthreads();

    int wid = tid >> 5, lane = tid & 31;
    int base = blockIdx.x * 256;
    int tap = lane & 3;
    int eo  = lane >> 2;   // 0..7

    #pragma unroll
    for (int it = 0; it < 4; it++) {
        int e_loc = wid * 32 + it * 8 + eo;
        int e = base + e_loc;
        if (e < EE) {
            int is = src[e], id = dst[e];
            const float4* Yp = reinterpret_cast<const float4*>(g_Y + e * 16);
            float Yv[16];
            #pragma unroll
            for (int q = 0; q < 4; q++) {
                float4 y4 = Yp[q];
                Yv[4*q]=y4.x; Yv[4*q+1]=y4.y; Yv[4*q+2]=y4.z; Yv[4*q+3]=y4.w;
            }
            const float4* Vd4 = reinterpret_cast<const float4*>(&g_Vi[(ll)id * 64 + tap * 16]);
            const float4* Vs4 = reinterpret_cast<const float4*>(&g_Vi[(ll)is * 64 + tap * 16]);
            float Vd[16], Vs[16];
            #pragma unroll
            for (int q = 0; q < 4; q++) {
                float4 a4 = Vd4[q], b4 = Vs4[q];
                Vd[4*q]=a4.x; Vd[4*q+1]=a4.y; Vd[4*q+2]=a4.z; Vd[4*q+3]=a4.w;
                Vs[4*q]=b4.x; Vs[4*q+1]=b4.y; Vs[4*q+2]=b4.z; Vs[4*q+3]=b4.w;
            }
            float u0 = (Vd[0] + Vs[0]) * Yv[0];
            float u1 = 0.f, u2 = 0.f, u3 = 0.f;
            #pragma unroll
            for (int m = 1; m < 4; m++)  u1 += (Vd[m] - Vs[m]) * Yv[m];
            #pragma unroll
            for (int m = 4; m < 9; m++)  u2 += (Vd[m] + Vs[m]) * Yv[m];
            #pragma unroll
            for (int m = 9; m < 16; m++) u3 += (Vd[m] - Vs[m]) * Yv[m];
            s_u2[ 0 + tap][e_loc] = u0;
            s_u2[ 4 + tap][e_loc] = u1;
            s_u2[ 8 + tap][e_loc] = u2;
            s_u2[12 + tap][e_loc] = u3;
        }
    }
    __syncthreads();

    int e = base + tid;
    if (e >= EE) return;
    float u[32];
    radial_eval(dist[e], u);
    #pragma unroll
    for (int j = 0; j < 16; j++) u[16 + j] = s_u2[j][tid];
    float w[16];
    mlp_eval<32>(u, s_pw1, s_b1, s_pw2, s_b2, w);
    float sws = swtch[e] * 0.25f;
    float4* wp = reinterpret_cast<float4*>(g_w + (ll)e * 16);
    #pragma unroll
    for (int d4 = 0; d4 < 4; d4++)
        wp[d4] = make_float4(w[4*d4] * sws, w[4*d4+1] * sws, w[4*d4+2] * sws, w[4*d4+3] * sws);
}

// ---------------- QKV SGEMM (double-buffered, head-transposed q/k out) ----------------
__global__ __launch_bounds__(256, 2) void sgemm_qkv_kernel(
    const float* __restrict__ wq, const float* __restrict__ wk,
    const float* __restrict__ wv)
{
    __shared__ u64   As2[2][16][128];
    __shared__ float Bs [2][16][128];
    int tid = threadIdx.x;
    int tx = tid & 15, ty = tid >> 4;
    int row0 = blockIdx.y * 128;
    int col0 = blockIdx.x * 128;
    u64 acc[8][4];
    #pragma unroll
    for (int i = 0; i < 8; i++)
        #pragma unroll
        for (int j = 0; j < 4; j++) acc[i][j] = 0ull;

    const int ar = tid >> 1;
    const int ac0 = (tid & 1) * 8;
    const int agrow = row0 + ar;
    const int bbr = tid >> 4;
    const int bbc = (tid & 15) * 8;
    const int bgcol = col0 + bbc;

    float4 pa0, pa1, pb0, pb1;
    {
        pa0 = make_float4(0,0,0,0); pa1 = make_float4(0,0,0,0);
        if (agrow < NN) {
            const float* s = g_xi + (ll)agrow * DIM + ac0;
            pa0 = *reinterpret_cast<const float4*>(s);
            pa1 = *reinterpret_cast<const float4*>(s + 4);
        }
        pb0 = make_float4(0,0,0,0); pb1 = make_float4(0,0,0,0);
        if (bgcol < QKVW) {
            const float* srcp; int c;
            if (bgcol < 320)      { srcp = wq + (ll)bbr * 320; c = bgcol; }
            else if (bgcol < 640) { srcp = wk + (ll)bbr * 320; c = bgcol - 320; }
            else                  { srcp = wv + (ll)bbr * 176; c = bgcol - 640; }
            pb0 = *reinterpret_cast<const float4*>(srcp + c);
            pb1 = *reinterpret_cast<const float4*>(srcp + c + 4);
        }
        As2[0][ac0+0][ar] = pack2(pa0.x, pa0.x);
        As2[0][ac0+1][ar] = pack2(pa0.y, pa0.y);
        As2[0][ac0+2][ar] = pack2(pa0.z, pa0.z);
        As2[0][ac0+3][ar] = pack2(pa0.w, pa0.w);
        As2[0][ac0+4][ar] = pack2(pa1.x, pa1.x);
        As2[0][ac0+5][ar] = pack2(pa1.y, pa1.y);
        As2[0][ac0+6][ar] = pack2(pa1.z, pa1.z);
        As2[0][ac0+7][ar] = pack2(pa1.w, pa1.w);
        *reinterpret_cast<float4*>(&Bs[0][bbr][bbc])     = pb0;
        *reinterpret_cast<float4*>(&Bs[0][bbr][bbc + 4]) = pb1;
    }
    __syncthreads();

    for (int kt = 0; kt < 11; ++kt) {
        int cur = kt & 1, nxt = cur ^ 1;
        bool has_nxt = (kt + 1 < 11);
        if (has_nxt) {
            int gkbase = (kt + 1) * 16;
            pa0 = make_float4(0,0,0,0); pa1 = make_float4(0,0,0,0);
            if (agrow < NN) {
                const float* s = g_xi + (ll)agrow * DIM + gkbase + ac0;
                pa0 = *reinterpret_cast<const float4*>(s);
                pa1 = *reinterpret_cast<const float4*>(s + 4);
            }
            int gk = gkbase + bbr;
            pb0 = make_float4(0,0,0,0); pb1 = make_float4(0,0,0,0);
            if (bgcol < QKVW) {
                const float* srcp; int c;
                if (bgcol < 320)      { srcp = wq + (ll)gk * 320; c = bgcol; }
                else if (bgcol < 640) { srcp = wk + (ll)gk * 320; c = bgcol - 320; }
                else                  { srcp = wv + (ll)gk * 176; c = bgcol - 640; }
                pb0 = *reinterpret_cast<const float4*>(srcp + c);
                pb1 = *reinterpret_cast<const float4*>(srcp + c + 4);
            }
        }
        #pragma unroll
        for (int k = 0; k < 16; ++k) {
            u64 a[8];
            {
                const ulonglong2* p = reinterpret_cast<const ulonglong2*>(&As2[cur][k][ty * 8]);
                ulonglong2 q0 = p[0], q1 = p[1], q2 = p[2], q3 = p[3];
                a[0]=q0.x; a[1]=q0.y; a[2]=q1.x; a[3]=q1.y;
                a[4]=q2.x; a[5]=q2.y; a[6]=q3.x; a[7]=q3.y;
            }
            u64 b[4];
            {
                const ulonglong2* p = reinterpret_cast<const ulonglong2*>(&Bs[cur][k][tx * 8]);
                ulonglong2 w0 = p[0], w1 = p[1];
                b[0]=w0.x; b[1]=w0.y; b[2]=w1.x; b[3]=w1.y;
            }
            #pragma unroll
            for (int i = 0; i < 8; i++)
                #pragma unroll
                for (int j = 0; j < 4; j++)
                    fma2(acc[i][j], a[i], b[j]);
        }
        if (has_nxt) {
            As2[nxt][ac0+0][ar] = pack2(pa0.x, pa0.x);
            As2[nxt][ac0+1][ar] = pack2(pa0.y, pa0.y);
            As2[nxt][ac0+2][ar] = pack2(pa0.z, pa0.z);
            As2[nxt][ac0+3][ar] = pack2(pa0.w, pa0.w);
            As2[nxt][ac0+4][ar] = pack2(pa1.x, pa1.x);
            As2[nxt][ac0+5][ar] = pack2(pa1.y, pa1.y);
            As2[nxt][ac0+6][ar] = pack2(pa1.z, pa1.z);
            As2[nxt][ac0+7][ar] = pack2(pa1.w, pa1.w);
            *reinterpret_cast<float4*>(&Bs[nxt][bbr][bbc])     = pb0;
            *reinterpret_cast<float4*>(&Bs[nxt][bbr][bbc + 4]) = pb1;
            __syncthreads();
        }
    }
    #pragma unroll
    for (int i = 0; i < 8; i++) {
        int gr = row0 + ty * 8 + i;
        if (gr >= NN) continue;
        #pragma unroll
        for (int j = 0; j < 4; j++) {
            int gc = col0 + tx * 8 + j * 2;
            if (gc < QKVW) {
                float2 f = unpack2(acc[i][j]);
                int oc;
                if (gc < 640) {
                    int blk = (gc < 320) ? 0 : 320;
                    int c = gc - blk;
                    int h = c >> 4, d = c & 15;
                    oc = blk + ((d >> 2) * 20 + h) * 4 + (d & 3);
                } else {
                    oc = gc;
                }
                *reinterpret_cast<float2*>(&g_qkv[(ll)gr * QKVW + oc]) = f;
            }
        }
    }
}

// ---------------- update SGEMM (double-buffered): G = [xi|mi] @ uw ----------------
__global__ __launch_bounds__(256, 2) void sgemm_upd_kernel(const float* __restrict__ B)
{
    __shared__ u64   As2[2][16][128];
    __shared__ float Bs [2][16][128];
    int tid = threadIdx.x;
    int tx = tid & 15, ty = tid >> 4;
    int row0 = blockIdx.y * 128;
    int col0 = blockIdx.x * 128;
    u64 acc[8][4];
    #pragma unroll
    for (int i = 0; i < 8; i++)
        #pragma unroll
        for (int j = 0; j < 4; j++) acc[i][j] = 0ull;

    const int ar = tid >> 1;
    const int ac0 = (tid & 1) * 8;
    const int agrow = row0 + ar;
    const int bbr = tid >> 4;
    const int bbc = (tid & 15) * 8;
    const int bgcol = col0 + bbc;

    float4 pa0, pa1, pb0, pb1;
    {
        pa0 = make_float4(0,0,0,0); pa1 = make_float4(0,0,0,0);
        if (agrow < NN) {
            const float* s = g_xi + (ll)agrow * DIM + ac0;
            pa0 = *reinterpret_cast<const float4*>(s);
            pa1 = *reinterpret_cast<const float4*>(s + 4);
        }
        pb0 = make_float4(0,0,0,0); pb1 = make_float4(0,0,0,0);
        if (bgcol < DIM) {
            const float* s = B + (ll)bbr * DIM + bgcol;
            pb0 = *reinterpret_cast<const float4*>(s);
            pb1 = *reinterpret_cast<const float4*>(s + 4);
        }
        As2[0][ac0+0][ar] = pack2(pa0.x, pa0.x);
        As2[0][ac0+1][ar] = pack2(pa0.y, pa0.y);
        As2[0][ac0+2][ar] = pack2(pa0.z, pa0.z);
        As2[0][ac0+3][ar] = pack2(pa0.w, pa0.w);
        As2[0][ac0+4][ar] = pack2(pa1.x, pa1.x);
        As2[0][ac0+5][ar] = pack2(pa1.y, pa1.y);
        As2[0][ac0+6][ar] = pack2(pa1.z, pa1.z);
        As2[0][ac0+7][ar] = pack2(pa1.w, pa1.w);
        *reinterpret_cast<float4*>(&Bs[0][bbr][bbc])     = pb0;
        *reinterpret_cast<float4*>(&Bs[0][bbr][bbc + 4]) = pb1;
    }
    __syncthreads();

    for (int kt = 0; kt < 22; ++kt) {
        int cur = kt & 1, nxt = cur ^ 1;
        bool has_nxt = (kt + 1 < 22);
        if (has_nxt) {
            int gkbase = (kt + 1) * 16;
            const float* Ap = (gkbase < DIM) ? g_xi : g_mi;
            int koff = (gkbase < DIM) ? gkbase : gkbase - DIM;
            pa0 = make_float4(0,0,0,0); pa1 = make_float4(0,0,0,0);
            if (agrow < NN) {
                const float* s = Ap + (ll)agrow * DIM + koff + ac0;
                pa0 = *reinterpret_cast<const float4*>(s);
                pa1 = *reinterpret_cast<const float4*>(s + 4);
            }
            int gk = gkbase + bbr;
            pb0 = make_float4(0,0,0,0); pb1 = make_float4(0,0,0,0);
            if (bgcol < DIM) {
                const float* s = B + (ll)gk * DIM + bgcol;
                pb0 = *reinterpret_cast<const float4*>(s);
                pb1 = *reinterpret_cast<const float4*>(s + 4);
            }
        }
        #pragma unroll
        for (int k = 0; k < 16; ++k) {
            u64 a[8];
            {
                const ulonglong2* p = reinterpret_cast<const ulonglong2*>(&As2[cur][k][ty * 8]);
                ulonglong2 q0 = p[0], q1 = p[1], q2 = p[2], q3 = p[3];
                a[0]=q0.x; a[1]=q0.y; a[2]=q1.x; a[3]=q1.y;
                a[4]=q2.x; a[5]=q2.y; a[6]=q3.x; a[7]=q3.y;
            }
            u64 b[4];
            {
                const ulonglong2* p = reinterpret_cast<const ulonglong2*>(&Bs[cur][k][tx * 8]);
                ulonglong2 w0 = p[0], w1 = p[1];
                b[0]=w0.x; b[1]=w0.y; b[2]=w1.x; b[3]=w1.y;
            }
            #pragma unroll
            for (int i = 0; i < 8; i++)
                #pragma unroll
                for (int j = 0; j < 4; j++)
                    fma2(acc[i][j], a[i], b[j]);
        }
        if (has_nxt) {
            As2[nxt][ac0+0][ar] = pack2(pa0.x, pa0.x);
            As2[nxt][ac0+1][ar] = pack2(pa0.y, pa0.y);
            As2[nxt][ac0+2][ar] = pack2(pa0.z, pa0.z);
            As2[nxt][ac0+3][ar] = pack2(pa0.w, pa0.w);
            As2[nxt][ac0+4][ar] = pack2(pa1.x, pa1.x);
            As2[nxt][ac0+5][ar] = pack2(pa1.y, pa1.y);
            As2[nxt][ac0+6][ar] = pack2(pa1.z, pa1.z);
            As2[nxt][ac0+7][ar] = pack2(pa1.w, pa1.w);
            *reinterpret_cast<float4*>(&Bs[nxt][bbr][bbc])     = pb0;
            *reinterpret_cast<float4*>(&Bs[nxt][bbr][bbc + 4]) = pb1;
            __syncthreads();
        }
    }
    #pragma unroll
    for (int i = 0; i < 8; i++) {
        int gr = row0 + ty * 8 + i;
        if (gr >= NN) continue;
        #pragma unroll
        for (int j = 0; j < 4; j++) {
            int gc = col0 + tx * 8 + j * 2;
            if (gc < DIM) {
                float2 f = unpack2(acc[i][j]);
                *reinterpret_cast<float2*>(&g_G[(ll)gr * DIM + gc]) = f;
            }
        }
    }
}

// ---------------- slim edge attention + scatter (grid-stride warp-per-edge) ----------------
template<int LAYER>
__global__ __launch_bounds__(256) void edge_attn_kernel(
    const int* __restrict__ src, const int* __restrict__ dst)
{
    __shared__ float s_a[8][20];

    int tid = threadIdx.x;
    int wid = tid >> 5, lane = tid & 31;
    int b0a = 4 * lane;
    int b0b = 4 * (lane + 32);
    int hA0 =  b0a      / VD, hA1 = (b0a + 1) / VD, hA2 = (b0a + 2) / VD, hA3 = (b0a + 3) / VD;
    int hB0 =  b0b      / VD, hB1 = (b0b + 1) / VD, hB2 = (b0b + 2) / VD, hB3 = (b0b + 3) / VD;

    for (int e = blockIdx.x * 8 + wid; e < EE; e += gridDim.x * 8) {
        int is = src[e], id = dst[e];
        float4 y4;
        if (LAYER == 0 && lane < 16)
            y4 = __ldg(reinterpret_cast<const float4*>(g_Y) + e * 4 + (lane & 3));
        const float4* qT = reinterpret_cast<const float4*>(g_qkv + (ll)id * QKVW);
        const float4* kT = reinterpret_cast<const float4*>(g_qkv + (ll)is * QKVW + 320);
        const float4* wp = reinterpret_cast<const float4*>(g_w + (ll)e * 16);
        // hoist v loads (independent of s_a) — overlap L2 latency with logit FMAs
        const float* vr = g_qkv + (ll)is * QKVW + 640;
        float4 v4a = *reinterpret_cast<const float4*>(vr + b0a);
        float4 v4b = make_float4(0, 0, 0, 0);
        if (lane < 12) v4b = *reinterpret_cast<const float4*>(vr + b0b);
        if (lane < 20) {
            float a0 = 0.f, a1 = 0.f;
            #pragma unroll
            for (int d4 = 0; d4 < 4; d4++) {
                float4 q4 = qT[d4 * 20 + lane];
                float4 k4 = kT[d4 * 20 + lane];
                float4 w4 = __ldg(wp + d4);
                a0 += q4.x * k4.x * w4.x + q4.y * k4.y * w4.y;
                a1 += q4.z * k4.z * w4.z + q4.w * k4.w * w4.w;
            }
            s_a[wid][lane] = a0 + a1;
        }
        __syncwarp();
        float* mr = &g_mi[(ll)id * DIM];
        {
            float4 o;
            o.x = s_a[wid][hA0] * v4a.x;
            o.y = s_a[wid][hA1] * v4a.y;
            o.z = s_a[wid][hA2] * v4a.z;
            o.w = s_a[wid][hA3] * v4a.w;
            atomicAdd(reinterpret_cast<float4*>(mr + b0a), o);
        }
        if (lane < 12) {
            float4 o;
            o.x = s_a[wid][hB0] * v4b.x;
            o.y = s_a[wid][hB1] * v4b.y;
            o.z = s_a[wid][hB2] * v4b.z;
            o.w = s_a[wid][hB3] * v4b.w;
            atomicAdd(reinterpret_cast<float4*>(mr + b0b), o);
        }
        if (LAYER == 0) {
            if (lane < 16) {
                float at = s_a[wid][16 + (lane >> 2)];
                float4 o = make_float4(at * y4.x, at * y4.y, at * y4.z, at * y4.w);
                atomicAdd(reinterpret_cast<float4*>(&g_Vi[(ll)id * 64 + 4 * lane]), o);
            }
        }
        __syncwarp();
    }
}

// ---------------- residual + LayerNorm (+ zero mi for next layer) ----------------
__global__ void resln_kernel(const float* __restrict__ ub, float* __restrict__ out, int toXi) {
    __shared__ float red[8];
    int n = blockIdx.x, t = threadIdx.x;
    float val = 0.f;
    if (t < DIM) val = g_xi[n * DIM + t] + g_G[n * DIM + t] + ub[t];
    float mu = block_sum_192(val, red) * (1.f / DIM);
    float dx = (t < DIM) ? (val - mu) : 0.f;
    float var = block_sum_192(dx * dx, red) * (1.f / DIM);
    if (t < DIM) {
        float o = dx * rsqrtf(var + 1e-6f);
        if (toXi) {
            g_xi[n * DIM + t] = o;
            g_mi[(ll)n * DIM + t] = 0.f;
        } else {
            out[n * DIM + t] = o;
        }
    }
}

// ---------------- launch ----------------
extern "C" void kernel_launch(void* const* d_in, const int* in_sizes, int n_in,
                              void* d_out, int out_size) {
    const int*   species  = (const int*)  d_in[0];
    const float* dist     = (const float*)d_in[1];
    const float* swtch    = (const float*)d_in[2];
    const int*   esrc     = (const int*)  d_in[3];
    const int*   edst     = (const int*)  d_in[4];
    const float* vec      = (const float*)d_in[5];
    const float* z_table  = (const float*)d_in[6];
    const float* w_sp     = (const float*)d_in[7];
    const float* pw1_0    = (const float*)d_in[8];
    const float* pb1_0    = (const float*)d_in[9];
    const float* pw2_0    = (const float*)d_in[10];
    const float* pb2_0    = (const float*)d_in[11];
    const float* wq_0     = (const float*)d_in[12];
    const float* wk_0     = (const float*)d_in[13];
    const float* wv_0     = (const float*)d_in[14];
    const float* uw_0     = (const float*)d_in[15];
    const float* ub_0     = (const float*)d_in[16];
    const float* pw1_1    = (const float*)d_in[17];
    const float* pb1_1    = (const float*)d_in[18];
    const float* pw2_1    = (const float*)d_in[19];
    const float* pb2_1    = (const float*)d_in[20];
    const float* wq_1     = (const float*)d_in[21];
    const float* wk_1     = (const float*)d_in[22];
    const float* wv_1     = (const float*)d_in[23];
    const float* uw_1     = (const float*)d_in[24];
    const float* ub_1     = (const float*)d_in[25];
    float* out = (float*)d_out;

    const int EB  = (EE + 255) / 256;
    const int EWB = 1184;
    dim3 grid_qkv(7, 79);
    dim3 grid_upd(2, 79);

    node_embed_kernel<<<NN, 192>>>(species, z_table, w_sp);                            // 0
    edge_geom_kernel<<<EB, 256>>>(dist, vec, swtch, pw1_0, pb1_0, pw2_0, pb2_0);       // 1

    // ---- layer 0 ----
    sgemm_qkv_kernel<<<grid_qkv, 256>>>(wq_0, wk_0, wv_0);                             // 2
    edge_attn_kernel<0><<<EWB, 256>>>(esrc, edst);                                     // 3 (profiled)
    sgemm_upd_kernel<<<grid_upd, 256>>>(uw_0);                                         // 4
    resln_kernel<<<NN, 192>>>(ub_0, out, 1);                                           // 5

    // ---- layer 1 ----
    ur1mlp1_kernel<<<EB, 256>>>(esrc, edst, dist, swtch, pw1_1, pb1_1, pw2_1, pb2_1);  // 6
    sgemm_qkv_kernel<<<grid_qkv, 256>>>(wq_1, wk_1, wv_1);                             // 7
    edge_attn_kernel<1><<<EWB, 256>>>(esrc, edst);                                     // 8
    sgemm_upd_kernel<<<grid_upd, 256>>>(uw_1);                                         // 9
    resln_kernel<<<NN, 192>>>(ub_1, out, 0);                                           // 10
}

// round 14
// speedup vs baseline: 1.2063x; 1.0910x over previous
#include <cuda_runtime.h>
#include <math.h>

#define NN   10000
#define EE   320000
#define DIM  176
#define ATT  16
#define SHH  16
#define THH  4
#define NHH  20
#define VD   11
#define NSPH 16
#define RDIMC 16
#define QKVW 816   // 320 + 320 + 176

typedef unsigned long long u64;
typedef long long ll;

// ---------------- scratch ----------------
__device__ float g_xi [NN * DIM];
__device__ float g_qkv[NN * QKVW];   // per node: qT[80 float4] | kT[80 float4] | v[176]
__device__ float g_mi [NN * DIM];
__device__ float g_Vi [NN * THH * NSPH];
__device__ float g_Y  [EE * NSPH];
__device__ float g_G  [NN * DIM];
__device__ float g_w  [(ll)EE * 16];   // per-edge MLP output (switch-scaled)

// ---------------- helpers ----------------
__device__ __forceinline__ u64 pack2(float x, float y) {
    u64 r; asm("mov.b64 %0,{%1,%2};" : "=l"(r) : "f"(x), "f"(y)); return r;
}
__device__ __forceinline__ void fma2(u64& d, u64 a, u64 b) {
    asm("fma.rn.f32x2 %0, %1, %2, %3;" : "=l"(d) : "l"(a), "l"(b), "l"(d));
}
__device__ __forceinline__ float2 unpack2(u64 v) {
    float2 f; asm("mov.b64 {%0,%1},%2;" : "=f"(f.x), "=f"(f.y) : "l"(v)); return f;
}

__device__ __forceinline__ float block_sum_192(float v, float* red) {
    #pragma unroll
    for (int o = 16; o; o >>= 1) v += __shfl_xor_sync(0xffffffffu, v, o);
    if ((threadIdx.x & 31) == 0) red[threadIdx.x >> 5] = v;
    __syncthreads();
    float s = 0.f;
    if (threadIdx.x < 6) s = red[threadIdx.x];
    if (threadIdx.x < 32) {
        s += __shfl_xor_sync(0xffffffffu, s, 4);
        s += __shfl_xor_sync(0xffffffffu, s, 2);
        s += __shfl_xor_sync(0xffffffffu, s, 1);
        if (threadIdx.x == 0) red[0] = s;
    }
    __syncthreads();
    float r = red[0];
    __syncthreads();
    return r;
}

// radial basis in registers
__device__ __forceinline__ void radial_eval(float d, float* R) {
    const float invs = 1.f / 0.28f;
    #pragma unroll
    for (int r = 0; r < 16; r++) {
        float c = 0.8f + 0.28f * (float)r;
        float tt = (d - c) * invs;
        R[r] = __expf(-tt * tt);
    }
}

// thread-local MLP: u[UR] -> w[16], weights in smem (float4 broadcast)
template<int UR>
__device__ __forceinline__ void mlp_eval(const float* u,
                                         const float4* s_pw1, const float* s_b1,
                                         const float4* s_pw2, const float* s_b2,
                                         float* w) {
    float h[32];
    #pragma unroll
    for (int j = 0; j < 32; j++) h[j] = s_b1[j];
    #pragma unroll
    for (int r = 0; r < UR; r++) {
        float uv = u[r];
        #pragma unroll
        for (int j4 = 0; j4 < 8; j4++) {
            float4 p = s_pw1[r * 8 + j4];
            h[4*j4+0] += uv * p.x; h[4*j4+1] += uv * p.y;
            h[4*j4+2] += uv * p.z; h[4*j4+3] += uv * p.w;
        }
    }
    #pragma unroll
    for (int j = 0; j < 32; j++) h[j] = h[j] / (1.f + __expf(-h[j]));
    #pragma unroll
    for (int d = 0; d < 16; d++) w[d] = s_b2[d];
    #pragma unroll
    for (int j = 0; j < 32; j++) {
        float hv = h[j];
        #pragma unroll
        for (int d4 = 0; d4 < 4; d4++) {
            float4 p = s_pw2[j * 4 + d4];
            w[4*d4+0] += hv * p.x; w[4*d4+1] += hv * p.y;
            w[4*d4+2] += hv * p.z; w[4*d4+3] += hv * p.w;
        }
    }
}

// ---------------- node embedding (+ zero mi, Vi for layer 0) ----------------
__global__ void node_embed_kernel(const int* __restrict__ species,
                                  const float* __restrict__ zt,
                                  const float* __restrict__ wsp) {
    __shared__ float sZ[16];
    __shared__ float red[8];
    int n = blockIdx.x;
    int t = threadIdx.x;
    if (t < DIM) g_mi[(ll)n * DIM + t] = 0.f;
    if (t < 64)  g_Vi[n * 64 + t] = 0.f;
    if (t < 16) sZ[t] = zt[species[n] * 16 + t];
    __syncthreads();
    float val = 0.f;
    if (t < DIM) {
        #pragma unroll
        for (int z = 0; z < 16; z++) val += sZ[z] * wsp[z * DIM + t];
    }
    float mu = block_sum_192(val, red) * (1.f / DIM);
    float dx = (t < DIM) ? (val - mu) : 0.f;
    float var = block_sum_192(dx * dx, red) * (1.f / DIM);
    if (t < DIM) g_xi[n * DIM + t] = dx * rsqrtf(var + 1e-6f);
}

// ---------------- edge geometry + fused layer-0 MLP (switch folded) ----------------
__global__ __launch_bounds__(256) void edge_geom_kernel(
    const float* __restrict__ dist, const float* __restrict__ vec,
    const float* __restrict__ swtch,
    const float* __restrict__ pw1, const float* __restrict__ pb1,
    const float* __restrict__ pw2, const float* __restrict__ pb2)
{
    __shared__ float4 s_pw1[128];   // 16x32
    __shared__ float4 s_pw2[128];   // 32x16
    __shared__ float  s_b1[32];
    __shared__ float  s_b2[16];
    int tid = threadIdx.x;
    for (int i = tid; i < 128; i += 256) {
        s_pw1[i] = reinterpret_cast<const float4*>(pw1)[i];
        s_pw2[i] = reinterpret_cast<const float4*>(pw2)[i];
    }
    if (tid < 32) s_b1[tid] = pb1[tid];
    if (tid < 16) s_b2[tid] = pb2[tid];
    __syncthreads();

    int e = blockIdx.x * blockDim.x + tid;
    if (e >= EE) return;
    float d = dist[e];
    float inv = 1.f / d;
    float x = vec[e * 3 + 0] * inv;
    float y = vec[e * 3 + 1] * inv;
    float z = vec[e * 3 + 2] * inv;
    const float s3  = 1.7320508075688772f;
    const float s15 = 3.872983346207417f;
    const float c1  = 0.7905694150420949f;
    const float c2  = 0.6123724356957945f;
    float x2 = x * x, y2 = y * y, z2 = z * z;
    float Y[16];
    Y[0]  = 1.f;
    Y[1]  = x; Y[2] = y; Y[3] = z;
    Y[4]  = s3 * x * y;
    Y[5]  = s3 * y * z;
    Y[6]  = 0.5f * (3.f * z2 - 1.f);
    Y[7]  = s3 * x * z;
    Y[8]  = 0.5f * s3 * (x2 - y2);
    Y[9]  = c1 * y * (3.f * x2 - y2);
    Y[10] = s15 * x * y * z;
    Y[11] = c2 * y * (5.f * z2 - 1.f);
    Y[12] = 0.5f * z * (5.f * z2 - 3.f);
    Y[13] = c2 * x * (5.f * z2 - 1.f);
    Y[14] = 0.5f * s15 * z * (x2 - y2);
    Y[15] = c1 * x * (x2 - 3.f * y2);
    float R[16];
    radial_eval(d, R);
    float4* yo = reinterpret_cast<float4*>(g_Y + e * 16);
    #pragma unroll
    for (int i = 0; i < 4; i++)
        yo[i] = make_float4(Y[4*i], Y[4*i+1], Y[4*i+2], Y[4*i+3]);
    float w[16];
    mlp_eval<16>(R, s_pw1, s_b1, s_pw2, s_b2, w);
    float sws = swtch[e] * 0.25f;
    float4* wp = reinterpret_cast<float4*>(g_w + (ll)e * 16);
    #pragma unroll
    for (int d4 = 0; d4 < 4; d4++)
        wp[d4] = make_float4(w[4*d4] * sws, w[4*d4+1] * sws, w[4*d4+2] * sws, w[4*d4+3] * sws);
}

// ---------------- fused layer-1 ur gather + MLP (parallel phase A) ----------------
#define U2PAD 264
__global__ __launch_bounds__(256) void ur1mlp1_kernel(
    const int* __restrict__ src, const int* __restrict__ dst,
    const float* __restrict__ dist, const float* __restrict__ swtch,
    const float* __restrict__ pw1, const float* __restrict__ pb1,
    const float* __restrict__ pw2, const float* __restrict__ pb2)
{
    __shared__ float4 s_pw1[256];   // 32x32
    __shared__ float4 s_pw2[128];   // 32x16
    __shared__ float  s_b1[32];
    __shared__ float  s_b2[16];
    __shared__ float  s_u2[16][U2PAD];

    int tid = threadIdx.x;
    for (int i = tid; i < 256; i += 256) s_pw1[i] = reinterpret_cast<const float4*>(pw1)[i];
    for (int i = tid; i < 128; i += 256) s_pw2[i] = reinterpret_cast<const float4*>(pw2)[i];
    if (tid < 32) s_b1[tid] = pb1[tid];
    if (tid < 16) s_b2[tid] = pb2[tid];
    __syncthreads();

    int wid = tid >> 5, lane = tid & 31;
    int base = blockIdx.x * 256;
    int tap = lane & 3;
    int eo  = lane >> 2;   // 0..7

    #pragma unroll
    for (int it = 0; it < 4; it++) {
        int e_loc = wid * 32 + it * 8 + eo;
        int e = base + e_loc;
        if (e < EE) {
            int is = src[e], id = dst[e];
            const float4* Yp = reinterpret_cast<const float4*>(g_Y + e * 16);
            float Yv[16];
            #pragma unroll
            for (int q = 0; q < 4; q++) {
                float4 y4 = Yp[q];
                Yv[4*q]=y4.x; Yv[4*q+1]=y4.y; Yv[4*q+2]=y4.z; Yv[4*q+3]=y4.w;
            }
            const float4* Vd4 = reinterpret_cast<const float4*>(&g_Vi[(ll)id * 64 + tap * 16]);
            const float4* Vs4 = reinterpret_cast<const float4*>(&g_Vi[(ll)is * 64 + tap * 16]);
            float Vd[16], Vs[16];
            #pragma unroll
            for (int q = 0; q < 4; q++) {
                float4 a4 = Vd4[q], b4 = Vs4[q];
                Vd[4*q]=a4.x; Vd[4*q+1]=a4.y; Vd[4*q+2]=a4.z; Vd[4*q+3]=a4.w;
                Vs[4*q]=b4.x; Vs[4*q+1]=b4.y; Vs[4*q+2]=b4.z; Vs[4*q+3]=b4.w;
            }
            float u0 = (Vd[0] + Vs[0]) * Yv[0];
            float u1 = 0.f, u2 = 0.f, u3 = 0.f;
            #pragma unroll
            for (int m = 1; m < 4; m++)  u1 += (Vd[m] - Vs[m]) * Yv[m];
            #pragma unroll
            for (int m = 4; m < 9; m++)  u2 += (Vd[m] + Vs[m]) * Yv[m];
            #pragma unroll
            for (int m = 9; m < 16; m++) u3 += (Vd[m] - Vs[m]) * Yv[m];
            s_u2[ 0 + tap][e_loc] = u0;
            s_u2[ 4 + tap][e_loc] = u1;
            s_u2[ 8 + tap][e_loc] = u2;
            s_u2[12 + tap][e_loc] = u3;
        }
    }
    __syncthreads();

    int e = base + tid;
    if (e >= EE) return;
    float u[32];
    radial_eval(dist[e], u);
    #pragma unroll
    for (int j = 0; j < 16; j++) u[16 + j] = s_u2[j][tid];
    float w[16];
    mlp_eval<32>(u, s_pw1, s_b1, s_pw2, s_b2, w);
    float sws = swtch[e] * 0.25f;
    float4* wp = reinterpret_cast<float4*>(g_w + (ll)e * 16);
    #pragma unroll
    for (int d4 = 0; d4 < 4; d4++)
        wp[d4] = make_float4(w[4*d4] * sws, w[4*d4+1] * sws, w[4*d4+2] * sws, w[4*d4+3] * sws);
}

// ---------------- QKV SGEMM (double-buffered, plain-A smem, head-transposed q/k out) ----------------
__global__ __launch_bounds__(256, 2) void sgemm_qkv_kernel(
    const float* __restrict__ wq, const float* __restrict__ wk,
    const float* __restrict__ wv)
{
    __shared__ float As[2][16][128];   // 16KB (plain A, dup in registers)
    __shared__ float Bs[2][16][128];   // 16KB
    int tid = threadIdx.x;
    int tx = tid & 15, ty = tid >> 4;
    int row0 = blockIdx.y * 128;
    int col0 = blockIdx.x * 128;
    u64 acc[8][4];
    #pragma unroll
    for (int i = 0; i < 8; i++)
        #pragma unroll
        for (int j = 0; j < 4; j++) acc[i][j] = 0ull;

    const int ar = tid >> 1;
    const int ac0 = (tid & 1) * 8;
    const int agrow = row0 + ar;
    const int bbr = tid >> 4;
    const int bbc = (tid & 15) * 8;
    const int bgcol = col0 + bbc;

    float4 pa0, pa1, pb0, pb1;
    {
        pa0 = make_float4(0,0,0,0); pa1 = make_float4(0,0,0,0);
        if (agrow < NN) {
            const float* s = g_xi + (ll)agrow * DIM + ac0;
            pa0 = *reinterpret_cast<const float4*>(s);
            pa1 = *reinterpret_cast<const float4*>(s + 4);
        }
        pb0 = make_float4(0,0,0,0); pb1 = make_float4(0,0,0,0);
        if (bgcol < QKVW) {
            const float* srcp; int c;
            if (bgcol < 320)      { srcp = wq + (ll)bbr * 320; c = bgcol; }
            else if (bgcol < 640) { srcp = wk + (ll)bbr * 320; c = bgcol - 320; }
            else                  { srcp = wv + (ll)bbr * 176; c = bgcol - 640; }
            pb0 = *reinterpret_cast<const float4*>(srcp + c);
            pb1 = *reinterpret_cast<const float4*>(srcp + c + 4);
        }
        As[0][ac0+0][ar] = pa0.x;
        As[0][ac0+1][ar] = pa0.y;
        As[0][ac0+2][ar] = pa0.z;
        As[0][ac0+3][ar] = pa0.w;
        As[0][ac0+4][ar] = pa1.x;
        As[0][ac0+5][ar] = pa1.y;
        As[0][ac0+6][ar] = pa1.z;
        As[0][ac0+7][ar] = pa1.w;
        *reinterpret_cast<float4*>(&Bs[0][bbr][bbc])     = pb0;
        *reinterpret_cast<float4*>(&Bs[0][bbr][bbc + 4]) = pb1;
    }
    __syncthreads();

    for (int kt = 0; kt < 11; ++kt) {
        int cur = kt & 1, nxt = cur ^ 1;
        bool has_nxt = (kt + 1 < 11);
        if (has_nxt) {
            int gkbase = (kt + 1) * 16;
            pa0 = make_float4(0,0,0,0); pa1 = make_float4(0,0,0,0);
            if (agrow < NN) {
                const float* s = g_xi + (ll)agrow * DIM + gkbase + ac0;
                pa0 = *reinterpret_cast<const float4*>(s);
                pa1 = *reinterpret_cast<const float4*>(s + 4);
            }
            int gk = gkbase + bbr;
            pb0 = make_float4(0,0,0,0); pb1 = make_float4(0,0,0,0);
            if (bgcol < QKVW) {
                const float* srcp; int c;
                if (bgcol < 320)      { srcp = wq + (ll)gk * 320; c = bgcol; }
                else if (bgcol < 640) { srcp = wk + (ll)gk * 320; c = bgcol - 320; }
                else                  { srcp = wv + (ll)gk * 176; c = bgcol - 640; }
                pb0 = *reinterpret_cast<const float4*>(srcp + c);
                pb1 = *reinterpret_cast<const float4*>(srcp + c + 4);
            }
        }
        #pragma unroll
        for (int k = 0; k < 16; ++k) {
            // plain-A load (2x LDS.128), duplicate into register pairs
            const float4* ap = reinterpret_cast<const float4*>(&As[cur][k][ty * 8]);
            float4 af0 = ap[0], af1 = ap[1];
            u64 a[8];
            a[0] = pack2(af0.x, af0.x); a[1] = pack2(af0.y, af0.y);
            a[2] = pack2(af0.z, af0.z); a[3] = pack2(af0.w, af0.w);
            a[4] = pack2(af1.x, af1.x); a[5] = pack2(af1.y, af1.y);
            a[6] = pack2(af1.z, af1.z); a[7] = pack2(af1.w, af1.w);
            u64 b[4];
            {
                const ulonglong2* p = reinterpret_cast<const ulonglong2*>(&Bs[cur][k][tx * 8]);
                ulonglong2 w0 = p[0], w1 = p[1];
                b[0]=w0.x; b[1]=w0.y; b[2]=w1.x; b[3]=w1.y;
            }
            #pragma unroll
            for (int i = 0; i < 8; i++)
                #pragma unroll
                for (int j = 0; j < 4; j++)
                    fma2(acc[i][j], a[i], b[j]);
        }
        if (has_nxt) {
            As[nxt][ac0+0][ar] = pa0.x;
            As[nxt][ac0+1][ar] = pa0.y;
            As[nxt][ac0+2][ar] = pa0.z;
            As[nxt][ac0+3][ar] = pa0.w;
            As[nxt][ac0+4][ar] = pa1.x;
            As[nxt][ac0+5][ar] = pa1.y;
            As[nxt][ac0+6][ar] = pa1.z;
            As[nxt][ac0+7][ar] = pa1.w;
            *reinterpret_cast<float4*>(&Bs[nxt][bbr][bbc])     = pb0;
            *reinterpret_cast<float4*>(&Bs[nxt][bbr][bbc + 4]) = pb1;
            __syncthreads();
        }
    }
    #pragma unroll
    for (int i = 0; i < 8; i++) {
        int gr = row0 + ty * 8 + i;
        if (gr >= NN) continue;
        #pragma unroll
        for (int j = 0; j < 4; j++) {
            int gc = col0 + tx * 8 + j * 2;
            if (gc < QKVW) {
                float2 f = unpack2(acc[i][j]);
                int oc;
                if (gc < 640) {
                    int blk = (gc < 320) ? 0 : 320;
                    int c = gc - blk;
                    int h = c >> 4, d = c & 15;
                    oc = blk + ((d >> 2) * 20 + h) * 4 + (d & 3);
                } else {
                    oc = gc;
                }
                *reinterpret_cast<float2*>(&g_qkv[(ll)gr * QKVW + oc]) = f;
            }
        }
    }
}

// ---------------- update SGEMM (double-buffered, plain-A smem): G = [xi|mi] @ uw ----------------
__global__ __launch_bounds__(256, 2) void sgemm_upd_kernel(const float* __restrict__ B)
{
    __shared__ float As[2][16][128];
    __shared__ float Bs[2][16][128];
    int tid = threadIdx.x;
    int tx = tid & 15, ty = tid >> 4;
    int row0 = blockIdx.y * 128;
    int col0 = blockIdx.x * 128;
    u64 acc[8][4];
    #pragma unroll
    for (int i = 0; i < 8; i++)
        #pragma unroll
        for (int j = 0; j < 4; j++) acc[i][j] = 0ull;

    const int ar = tid >> 1;
    const int ac0 = (tid & 1) * 8;
    const int agrow = row0 + ar;
    const int bbr = tid >> 4;
    const int bbc = (tid & 15) * 8;
    const int bgcol = col0 + bbc;

    float4 pa0, pa1, pb0, pb1;
    {
        pa0 = make_float4(0,0,0,0); pa1 = make_float4(0,0,0,0);
        if (agrow < NN) {
            const float* s = g_xi + (ll)agrow * DIM + ac0;
            pa0 = *reinterpret_cast<const float4*>(s);
            pa1 = *reinterpret_cast<const float4*>(s + 4);
        }
        pb0 = make_float4(0,0,0,0); pb1 = make_float4(0,0,0,0);
        if (bgcol < DIM) {
            const float* s = B + (ll)bbr * DIM + bgcol;
            pb0 = *reinterpret_cast<const float4*>(s);
            pb1 = *reinterpret_cast<const float4*>(s + 4);
        }
        As[0][ac0+0][ar] = pa0.x;
        As[0][ac0+1][ar] = pa0.y;
        As[0][ac0+2][ar] = pa0.z;
        As[0][ac0+3][ar] = pa0.w;
        As[0][ac0+4][ar] = pa1.x;
        As[0][ac0+5][ar] = pa1.y;
        As[0][ac0+6][ar] = pa1.z;
        As[0][ac0+7][ar] = pa1.w;
        *reinterpret_cast<float4*>(&Bs[0][bbr][bbc])     = pb0;
        *reinterpret_cast<float4*>(&Bs[0][bbr][bbc + 4]) = pb1;
    }
    __syncthreads();

    for (int kt = 0; kt < 22; ++kt) {
        int cur = kt & 1, nxt = cur ^ 1;
        bool has_nxt = (kt + 1 < 22);
        if (has_nxt) {
            int gkbase = (kt + 1) * 16;
            const float* Ap = (gkbase < DIM) ? g_xi : g_mi;
            int koff = (gkbase < DIM) ? gkbase : gkbase - DIM;
            pa0 = make_float4(0,0,0,0); pa1 = make_float4(0,0,0,0);
            if (agrow < NN) {
                const float* s = Ap + (ll)agrow * DIM + koff + ac0;
                pa0 = *reinterpret_cast<const float4*>(s);
                pa1 = *reinterpret_cast<const float4*>(s + 4);
            }
            int gk = gkbase + bbr;
            pb0 = make_float4(0,0,0,0); pb1 = make_float4(0,0,0,0);
            if (bgcol < DIM) {
                const float* s = B + (ll)gk * DIM + bgcol;
                pb0 = *reinterpret_cast<const float4*>(s);
                pb1 = *reinterpret_cast<const float4*>(s + 4);
            }
        }
        #pragma unroll
        for (int k = 0; k < 16; ++k) {
            const float4* ap = reinterpret_cast<const float4*>(&As[cur][k][ty * 8]);
            float4 af0 = ap[0], af1 = ap[1];
            u64 a[8];
            a[0] = pack2(af0.x, af0.x); a[1] = pack2(af0.y, af0.y);
            a[2] = pack2(af0.z, af0.z); a[3] = pack2(af0.w, af0.w);
            a[4] = pack2(af1.x, af1.x); a[5] = pack2(af1.y, af1.y);
            a[6] = pack2(af1.z, af1.z); a[7] = pack2(af1.w, af1.w);
            u64 b[4];
            {
                const ulonglong2* p = reinterpret_cast<const ulonglong2*>(&Bs[cur][k][tx * 8]);
                ulonglong2 w0 = p[0], w1 = p[1];
                b[0]=w0.x; b[1]=w0.y; b[2]=w1.x; b[3]=w1.y;
            }
            #pragma unroll
            for (int i = 0; i < 8; i++)
                #pragma unroll
                for (int j = 0; j < 4; j++)
                    fma2(acc[i][j], a[i], b[j]);
        }
        if (has_nxt) {
            As[nxt][ac0+0][ar] = pa0.x;
            As[nxt][ac0+1][ar] = pa0.y;
            As[nxt][ac0+2][ar] = pa0.z;
            As[nxt][ac0+3][ar] = pa0.w;
            As[nxt][ac0+4][ar] = pa1.x;
            As[nxt][ac0+5][ar] = pa1.y;
            As[nxt][ac0+6][ar] = pa1.z;
            As[nxt][ac0+7][ar] = pa1.w;
            *reinterpret_cast<float4*>(&Bs[nxt][bbr][bbc])     = pb0;
            *reinterpret_cast<float4*>(&Bs[nxt][bbr][bbc + 4]) = pb1;
            __syncthreads();
        }
    }
    #pragma unroll
    for (int i = 0; i < 8; i++) {
        int gr = row0 + ty * 8 + i;
        if (gr >= NN) continue;
        #pragma unroll
        for (int j = 0; j < 4; j++) {
            int gc = col0 + tx * 8 + j * 2;
            if (gc < DIM) {
                float2 f = unpack2(acc[i][j]);
                *reinterpret_cast<float2*>(&g_G[(ll)gr * DIM + gc]) = f;
            }
        }
    }
}

// ---------------- slim edge attention + scatter (grid-stride warp-per-edge) ----------------
template<int LAYER>
__global__ __launch_bounds__(256) void edge_attn_kernel(
    const int* __restrict__ src, const int* __restrict__ dst)
{
    __shared__ float s_a[8][20];

    int tid = threadIdx.x;
    int wid = tid >> 5, lane = tid & 31;
    int b0a = 4 * lane;
    int b0b = 4 * (lane + 32);
    int hA0 =  b0a      / VD, hA1 = (b0a + 1) / VD, hA2 = (b0a + 2) / VD, hA3 = (b0a + 3) / VD;
    int hB0 =  b0b      / VD, hB1 = (b0b + 1) / VD, hB2 = (b0b + 2) / VD, hB3 = (b0b + 3) / VD;

    for (int e = blockIdx.x * 8 + wid; e < EE; e += gridDim.x * 8) {
        int is = src[e], id = dst[e];
        float4 y4;
        if (LAYER == 0 && lane < 16)
            y4 = __ldg(reinterpret_cast<const float4*>(g_Y) + e * 4 + (lane & 3));
        const float4* qT = reinterpret_cast<const float4*>(g_qkv + (ll)id * QKVW);
        const float4* kT = reinterpret_cast<const float4*>(g_qkv + (ll)is * QKVW + 320);
        const float4* wp = reinterpret_cast<const float4*>(g_w + (ll)e * 16);
        // hoist v loads (independent of s_a) — overlap L2 latency with logit FMAs
        const float* vr = g_qkv + (ll)is * QKVW + 640;
        float4 v4a = *reinterpret_cast<const float4*>(vr + b0a);
        float4 v4b = make_float4(0, 0, 0, 0);
        if (lane < 12) v4b = *reinterpret_cast<const float4*>(vr + b0b);
        if (lane < 20) {
            float a0 = 0.f, a1 = 0.f;
            #pragma unroll
            for (int d4 = 0; d4 < 4; d4++) {
                float4 q4 = qT[d4 * 20 + lane];
                float4 k4 = kT[d4 * 20 + lane];
                float4 w4 = __ldg(wp + d4);
                a0 += q4.x * k4.x * w4.x + q4.y * k4.y * w4.y;
                a1 += q4.z * k4.z * w4.z + q4.w * k4.w * w4.w;
            }
            s_a[wid][lane] = a0 + a1;
        }
        __syncwarp();
        float* mr = &g_mi[(ll)id * DIM];
        {
            float4 o;
            o.x = s_a[wid][hA0] * v4a.x;
            o.y = s_a[wid][hA1] * v4a.y;
            o.z = s_a[wid][hA2] * v4a.z;
            o.w = s_a[wid][hA3] * v4a.w;
            atomicAdd(reinterpret_cast<float4*>(mr + b0a), o);
        }
        if (lane < 12) {
            float4 o;
            o.x = s_a[wid][hB0] * v4b.x;
            o.y = s_a[wid][hB1] * v4b.y;
            o.z = s_a[wid][hB2] * v4b.z;
            o.w = s_a[wid][hB3] * v4b.w;
            atomicAdd(reinterpret_cast<float4*>(mr + b0b), o);
        }
        if (LAYER == 0) {
            if (lane < 16) {
                float at = s_a[wid][16 + (lane >> 2)];
                float4 o = make_float4(at * y4.x, at * y4.y, at * y4.z, at * y4.w);
                atomicAdd(reinterpret_cast<float4*>(&g_Vi[(ll)id * 64 + 4 * lane]), o);
            }
        }
        __syncwarp();
    }
}

// ---------------- residual + LayerNorm (+ zero mi for next layer) ----------------
__global__ void resln_kernel(const float* __restrict__ ub, float* __restrict__ out, int toXi) {
    __shared__ float red[8];
    int n = blockIdx.x, t = threadIdx.x;
    float val = 0.f;
    if (t < DIM) val = g_xi[n * DIM + t] + g_G[n * DIM + t] + ub[t];
    float mu = block_sum_192(val, red) * (1.f / DIM);
    float dx = (t < DIM) ? (val - mu) : 0.f;
    float var = block_sum_192(dx * dx, red) * (1.f / DIM);
    if (t < DIM) {
        float o = dx * rsqrtf(var + 1e-6f);
        if (toXi) {
            g_xi[n * DIM + t] = o;
            g_mi[(ll)n * DIM + t] = 0.f;
        } else {
            out[n * DIM + t] = o;
        }
    }
}

// ---------------- launch ----------------
extern "C" void kernel_launch(void* const* d_in, const int* in_sizes, int n_in,
                              void* d_out, int out_size) {
    const int*   species  = (const int*)  d_in[0];
    const float* dist     = (const float*)d_in[1];
    const float* swtch    = (const float*)d_in[2];
    const int*   esrc     = (const int*)  d_in[3];
    const int*   edst     = (const int*)  d_in[4];
    const float* vec      = (const float*)d_in[5];
    const float* z_table  = (const float*)d_in[6];
    const float* w_sp     = (const float*)d_in[7];
    const float* pw1_0    = (const float*)d_in[8];
    const float* pb1_0    = (const float*)d_in[9];
    const float* pw2_0    = (const float*)d_in[10];
    const float* pb2_0    = (const float*)d_in[11];
    const float* wq_0     = (const float*)d_in[12];
    const float* wk_0     = (const float*)d_in[13];
    const float* wv_0     = (const float*)d_in[14];
    const float* uw_0     = (const float*)d_in[15];
    const float* ub_0     = (const float*)d_in[16];
    const float* pw1_1    = (const float*)d_in[17];
    const float* pb1_1    = (const float*)d_in[18];
    const float* pw2_1    = (const float*)d_in[19];
    const float* pb2_1    = (const float*)d_in[20];
    const float* wq_1     = (const float*)d_in[21];
    const float* wk_1     = (const float*)d_in[22];
    const float* wv_1     = (const float*)d_in[23];
    const float* uw_1     = (const float*)d_in[24];
    const float* ub_1     = (const float*)d_in[25];
    float* out = (float*)d_out;

    const int EB  = (EE + 255) / 256;
    const int EWB = 1184;
    dim3 grid_qkv(7, 79);
    dim3 grid_upd(2, 79);

    node_embed_kernel<<<NN, 192>>>(species, z_table, w_sp);                            // 0
    edge_geom_kernel<<<EB, 256>>>(dist, vec, swtch, pw1_0, pb1_0, pw2_0, pb2_0);       // 1

    // ---- layer 0 ----
    sgemm_qkv_kernel<<<grid_qkv, 256>>>(wq_0, wk_0, wv_0);                             // 2
    edge_attn_kernel<0><<<EWB, 256>>>(esrc, edst);                                     // 3 (profiled)
    sgemm_upd_kernel<<<grid_upd, 256>>>(uw_0);                                         // 4
    resln_kernel<<<NN, 192>>>(ub_0, out, 1);                                           // 5

    // ---- layer 1 ----
    ur1mlp1_kernel<<<EB, 256>>>(esrc, edst, dist, swtch, pw1_1, pb1_1, pw2_1, pb2_1);  // 6
    sgemm_qkv_kernel<<<grid_qkv, 256>>>(wq_1, wk_1, wv_1);                             // 7
    edge_attn_kernel<1><<<EWB, 256>>>(esrc, edst);                                     // 8
    sgemm_upd_kernel<<<grid_upd, 256>>>(uw_1);                                         // 9
    resln_kernel<<<NN, 192>>>(ub_1, out, 0);                                           // 10
}

// round 15
// speedup vs baseline: 1.2231x; 1.0139x over previous
#include <cuda_runtime.h>
#include <cuda_fp16.h>
#include <math.h>

#define NN   10000
#define EE   320000
#define DIM  176
#define ATT  16
#define SHH  16
#define THH  4
#define NHH  20
#define VD   11
#define NSPH 16
#define RDIMC 16
#define QKVW 816   // 320 + 320 + 176 (GEMM column space)

typedef unsigned long long u64;
typedef long long ll;

// ---------------- scratch ----------------
__device__ float  g_xi [NN * DIM];
__device__ __half g_qkh[NN * 640];   // per node: qT[320 half] | kT[320 half], head-transposed
__device__ float  g_v  [NN * DIM];   // per node: v[176] fp32
__device__ float  g_mi [NN * DIM];
__device__ float  g_Vi [NN * THH * NSPH];
__device__ float  g_Y  [EE * NSPH];
__device__ float  g_G  [NN * DIM];
__device__ float  g_w  [(ll)EE * 16];   // per-edge MLP output (switch-scaled)

// ---------------- helpers ----------------
__device__ __forceinline__ u64 pack2(float x, float y) {
    u64 r; asm("mov.b64 %0,{%1,%2};" : "=l"(r) : "f"(x), "f"(y)); return r;
}
__device__ __forceinline__ void fma2(u64& d, u64 a, u64 b) {
    asm("fma.rn.f32x2 %0, %1, %2, %3;" : "=l"(d) : "l"(a), "l"(b), "l"(d));
}
__device__ __forceinline__ float2 unpack2(u64 v) {
    float2 f; asm("mov.b64 {%0,%1},%2;" : "=f"(f.x), "=f"(f.y) : "l"(v)); return f;
}

__device__ __forceinline__ float block_sum_192(float v, float* red) {
    #pragma unroll
    for (int o = 16; o; o >>= 1) v += __shfl_xor_sync(0xffffffffu, v, o);
    if ((threadIdx.x & 31) == 0) red[threadIdx.x >> 5] = v;
    __syncthreads();
    float s = 0.f;
    if (threadIdx.x < 6) s = red[threadIdx.x];
    if (threadIdx.x < 32) {
        s += __shfl_xor_sync(0xffffffffu, s, 4);
        s += __shfl_xor_sync(0xffffffffu, s, 2);
        s += __shfl_xor_sync(0xffffffffu, s, 1);
        if (threadIdx.x == 0) red[0] = s;
    }
    __syncthreads();
    float r = red[0];
    __syncthreads();
    return r;
}

// radial basis in registers
__device__ __forceinline__ void radial_eval(float d, float* R) {
    const float invs = 1.f / 0.28f;
    #pragma unroll
    for (int r = 0; r < 16; r++) {
        float c = 0.8f + 0.28f * (float)r;
        float tt = (d - c) * invs;
        R[r] = __expf(-tt * tt);
    }
}

// thread-local MLP: u[UR] -> w[16], weights in smem (float4 broadcast)
template<int UR>
__device__ __forceinline__ void mlp_eval(const float* u,
                                         const float4* s_pw1, const float* s_b1,
                                         const float4* s_pw2, const float* s_b2,
                                         float* w) {
    float h[32];
    #pragma unroll
    for (int j = 0; j < 32; j++) h[j] = s_b1[j];
    #pragma unroll
    for (int r = 0; r < UR; r++) {
        float uv = u[r];
        #pragma unroll
        for (int j4 = 0; j4 < 8; j4++) {
            float4 p = s_pw1[r * 8 + j4];
            h[4*j4+0] += uv * p.x; h[4*j4+1] += uv * p.y;
            h[4*j4+2] += uv * p.z; h[4*j4+3] += uv * p.w;
        }
    }
    #pragma unroll
    for (int j = 0; j < 32; j++) h[j] = h[j] / (1.f + __expf(-h[j]));
    #pragma unroll
    for (int d = 0; d < 16; d++) w[d] = s_b2[d];
    #pragma unroll
    for (int j = 0; j < 32; j++) {
        float hv = h[j];
        #pragma unroll
        for (int d4 = 0; d4 < 4; d4++) {
            float4 p = s_pw2[j * 4 + d4];
            w[4*d4+0] += hv * p.x; w[4*d4+1] += hv * p.y;
            w[4*d4+2] += hv * p.z; w[4*d4+3] += hv * p.w;
        }
    }
}

// ---------------- node embedding (+ zero mi, Vi for layer 0) ----------------
__global__ void node_embed_kernel(const int* __restrict__ species,
                                  const float* __restrict__ zt,
                                  const float* __restrict__ wsp) {
    __shared__ float sZ[16];
    __shared__ float red[8];
    int n = blockIdx.x;
    int t = threadIdx.x;
    if (t < DIM) g_mi[(ll)n * DIM + t] = 0.f;
    if (t < 64)  g_Vi[n * 64 + t] = 0.f;
    if (t < 16) sZ[t] = zt[species[n] * 16 + t];
    __syncthreads();
    float val = 0.f;
    if (t < DIM) {
        #pragma unroll
        for (int z = 0; z < 16; z++) val += sZ[z] * wsp[z * DIM + t];
    }
    float mu = block_sum_192(val, red) * (1.f / DIM);
    float dx = (t < DIM) ? (val - mu) : 0.f;
    float var = block_sum_192(dx * dx, red) * (1.f / DIM);
    if (t < DIM) g_xi[n * DIM + t] = dx * rsqrtf(var + 1e-6f);
}

// ---------------- edge geometry + fused layer-0 MLP (switch folded) ----------------
__global__ __launch_bounds__(256) void edge_geom_kernel(
    const float* __restrict__ dist, const float* __restrict__ vec,
    const float* __restrict__ swtch,
    const float* __restrict__ pw1, const float* __restrict__ pb1,
    const float* __restrict__ pw2, const float* __restrict__ pb2)
{
    __shared__ float4 s_pw1[128];   // 16x32
    __shared__ float4 s_pw2[128];   // 32x16
    __shared__ float  s_b1[32];
    __shared__ float  s_b2[16];
    int tid = threadIdx.x;
    for (int i = tid; i < 128; i += 256) {
        s_pw1[i] = reinterpret_cast<const float4*>(pw1)[i];
        s_pw2[i] = reinterpret_cast<const float4*>(pw2)[i];
    }
    if (tid < 32) s_b1[tid] = pb1[tid];
    if (tid < 16) s_b2[tid] = pb2[tid];
    __syncthreads();

    int e = blockIdx.x * blockDim.x + tid;
    if (e >= EE) return;
    float d = dist[e];
    float inv = 1.f / d;
    float x = vec[e * 3 + 0] * inv;
    float y = vec[e * 3 + 1] * inv;
    float z = vec[e * 3 + 2] * inv;
    const float s3  = 1.7320508075688772f;
    const float s15 = 3.872983346207417f;
    const float c1  = 0.7905694150420949f;
    const float c2  = 0.6123724356957945f;
    float x2 = x * x, y2 = y * y, z2 = z * z;
    float Y[16];
    Y[0]  = 1.f;
    Y[1]  = x; Y[2] = y; Y[3] = z;
    Y[4]  = s3 * x * y;
    Y[5]  = s3 * y * z;
    Y[6]  = 0.5f * (3.f * z2 - 1.f);
    Y[7]  = s3 * x * z;
    Y[8]  = 0.5f * s3 * (x2 - y2);
    Y[9]  = c1 * y * (3.f * x2 - y2);
    Y[10] = s15 * x * y * z;
    Y[11] = c2 * y * (5.f * z2 - 1.f);
    Y[12] = 0.5f * z * (5.f * z2 - 3.f);
    Y[13] = c2 * x * (5.f * z2 - 1.f);
    Y[14] = 0.5f * s15 * z * (x2 - y2);
    Y[15] = c1 * x * (x2 - 3.f * y2);
    float R[16];
    radial_eval(d, R);
    float4* yo = reinterpret_cast<float4*>(g_Y + e * 16);
    #pragma unroll
    for (int i = 0; i < 4; i++)
        yo[i] = make_float4(Y[4*i], Y[4*i+1], Y[4*i+2], Y[4*i+3]);
    float w[16];
    mlp_eval<16>(R, s_pw1, s_b1, s_pw2, s_b2, w);
    float sws = swtch[e] * 0.25f;
    float4* wp = reinterpret_cast<float4*>(g_w + (ll)e * 16);
    #pragma unroll
    for (int d4 = 0; d4 < 4; d4++)
        wp[d4] = make_float4(w[4*d4] * sws, w[4*d4+1] * sws, w[4*d4+2] * sws, w[4*d4+3] * sws);
}

// ---------------- fused layer-1 ur gather + MLP (parallel phase A) ----------------
#define U2PAD 264
__global__ __launch_bounds__(256) void ur1mlp1_kernel(
    const int* __restrict__ src, const int* __restrict__ dst,
    const float* __restrict__ dist, const float* __restrict__ swtch,
    const float* __restrict__ pw1, const float* __restrict__ pb1,
    const float* __restrict__ pw2, const float* __restrict__ pb2)
{
    __shared__ float4 s_pw1[256];   // 32x32
    __shared__ float4 s_pw2[128];   // 32x16
    __shared__ float  s_b1[32];
    __shared__ float  s_b2[16];
    __shared__ float  s_u2[16][U2PAD];

    int tid = threadIdx.x;
    for (int i = tid; i < 256; i += 256) s_pw1[i] = reinterpret_cast<const float4*>(pw1)[i];
    for (int i = tid; i < 128; i += 256) s_pw2[i] = reinterpret_cast<const float4*>(pw2)[i];
    if (tid < 32) s_b1[tid] = pb1[tid];
    if (tid < 16) s_b2[tid] = pb2[tid];
    __syncthreads();

    int wid = tid >> 5, lane = tid & 31;
    int base = blockIdx.x * 256;
    int tap = lane & 3;
    int eo  = lane >> 2;   // 0..7

    #pragma unroll
    for (int it = 0; it < 4; it++) {
        int e_loc = wid * 32 + it * 8 + eo;
        int e = base + e_loc;
        if (e < EE) {
            int is = src[e], id = dst[e];
            const float4* Yp = reinterpret_cast<const float4*>(g_Y + e * 16);
            float Yv[16];
            #pragma unroll
            for (int q = 0; q < 4; q++) {
                float4 y4 = Yp[q];
                Yv[4*q]=y4.x; Yv[4*q+1]=y4.y; Yv[4*q+2]=y4.z; Yv[4*q+3]=y4.w;
            }
            const float4* Vd4 = reinterpret_cast<const float4*>(&g_Vi[(ll)id * 64 + tap * 16]);
            const float4* Vs4 = reinterpret_cast<const float4*>(&g_Vi[(ll)is * 64 + tap * 16]);
            float Vd[16], Vs[16];
            #pragma unroll
            for (int q = 0; q < 4; q++) {
                float4 a4 = Vd4[q], b4 = Vs4[q];
                Vd[4*q]=a4.x; Vd[4*q+1]=a4.y; Vd[4*q+2]=a4.z; Vd[4*q+3]=a4.w;
                Vs[4*q]=b4.x; Vs[4*q+1]=b4.y; Vs[4*q+2]=b4.z; Vs[4*q+3]=b4.w;
            }
            float u0 = (Vd[0] + Vs[0]) * Yv[0];
            float u1 = 0.f, u2 = 0.f, u3 = 0.f;
            #pragma unroll
            for (int m = 1; m < 4; m++)  u1 += (Vd[m] - Vs[m]) * Yv[m];
            #pragma unroll
            for (int m = 4; m < 9; m++)  u2 += (Vd[m] + Vs[m]) * Yv[m];
            #pragma unroll
            for (int m = 9; m < 16; m++) u3 += (Vd[m] - Vs[m]) * Yv[m];
            s_u2[ 0 + tap][e_loc] = u0;
            s_u2[ 4 + tap][e_loc] = u1;
            s_u2[ 8 + tap][e_loc] = u2;
            s_u2[12 + tap][e_loc] = u3;
        }
    }
    __syncthreads();

    int e = base + tid;
    if (e >= EE) return;
    float u[32];
    radial_eval(dist[e], u);
    #pragma unroll
    for (int j = 0; j < 16; j++) u[16 + j] = s_u2[j][tid];
    float w[16];
    mlp_eval<32>(u, s_pw1, s_b1, s_pw2, s_b2, w);
    float sws = swtch[e] * 0.25f;
    float4* wp = reinterpret_cast<float4*>(g_w + (ll)e * 16);
    #pragma unroll
    for (int d4 = 0; d4 < 4; d4++)
        wp[d4] = make_float4(w[4*d4] * sws, w[4*d4+1] * sws, w[4*d4+2] * sws, w[4*d4+3] * sws);
}

// ---------------- QKV SGEMM (double-buffered, plain-A smem, fp16 q/k out) ----------------
__global__ __launch_bounds__(256, 2) void sgemm_qkv_kernel(
    const float* __restrict__ wq, const float* __restrict__ wk,
    const float* __restrict__ wv)
{
    __shared__ float As[2][16][128];
    __shared__ float Bs[2][16][128];
    int tid = threadIdx.x;
    int tx = tid & 15, ty = tid >> 4;
    int row0 = blockIdx.y * 128;
    int col0 = blockIdx.x * 128;
    u64 acc[8][4];
    #pragma unroll
    for (int i = 0; i < 8; i++)
        #pragma unroll
        for (int j = 0; j < 4; j++) acc[i][j] = 0ull;

    const int ar = tid >> 1;
    const int ac0 = (tid & 1) * 8;
    const int agrow = row0 + ar;
    const int bbr = tid >> 4;
    const int bbc = (tid & 15) * 8;
    const int bgcol = col0 + bbc;

    float4 pa0, pa1, pb0, pb1;
    {
        pa0 = make_float4(0,0,0,0); pa1 = make_float4(0,0,0,0);
        if (agrow < NN) {
            const float* s = g_xi + (ll)agrow * DIM + ac0;
            pa0 = *reinterpret_cast<const float4*>(s);
            pa1 = *reinterpret_cast<const float4*>(s + 4);
        }
        pb0 = make_float4(0,0,0,0); pb1 = make_float4(0,0,0,0);
        if (bgcol < QKVW) {
            const float* srcp; int c;
            if (bgcol < 320)      { srcp = wq + (ll)bbr * 320; c = bgcol; }
            else if (bgcol < 640) { srcp = wk + (ll)bbr * 320; c = bgcol - 320; }
            else                  { srcp = wv + (ll)bbr * 176; c = bgcol - 640; }
            pb0 = *reinterpret_cast<const float4*>(srcp + c);
            pb1 = *reinterpret_cast<const float4*>(srcp + c + 4);
        }
        As[0][ac0+0][ar] = pa0.x;
        As[0][ac0+1][ar] = pa0.y;
        As[0][ac0+2][ar] = pa0.z;
        As[0][ac0+3][ar] = pa0.w;
        As[0][ac0+4][ar] = pa1.x;
        As[0][ac0+5][ar] = pa1.y;
        As[0][ac0+6][ar] = pa1.z;
        As[0][ac0+7][ar] = pa1.w;
        *reinterpret_cast<float4*>(&Bs[0][bbr][bbc])     = pb0;
        *reinterpret_cast<float4*>(&Bs[0][bbr][bbc + 4]) = pb1;
    }
    __syncthreads();

    for (int kt = 0; kt < 11; ++kt) {
        int cur = kt & 1, nxt = cur ^ 1;
        bool has_nxt = (kt + 1 < 11);
        if (has_nxt) {
            int gkbase = (kt + 1) * 16;
            pa0 = make_float4(0,0,0,0); pa1 = make_float4(0,0,0,0);
            if (agrow < NN) {
                const float* s = g_xi + (ll)agrow * DIM + gkbase + ac0;
                pa0 = *reinterpret_cast<const float4*>(s);
                pa1 = *reinterpret_cast<const float4*>(s + 4);
            }
            int gk = gkbase + bbr;
            pb0 = make_float4(0,0,0,0); pb1 = make_float4(0,0,0,0);
            if (bgcol < QKVW) {
                const float* srcp; int c;
                if (bgcol < 320)      { srcp = wq + (ll)gk * 320; c = bgcol; }
                else if (bgcol < 640) { srcp = wk + (ll)gk * 320; c = bgcol - 320; }
                else                  { srcp = wv + (ll)gk * 176; c = bgcol - 640; }
                pb0 = *reinterpret_cast<const float4*>(srcp + c);
                pb1 = *reinterpret_cast<const float4*>(srcp + c + 4);
            }
        }
        #pragma unroll
        for (int k = 0; k < 16; ++k) {
            const float4* ap = reinterpret_cast<const float4*>(&As[cur][k][ty * 8]);
            float4 af0 = ap[0], af1 = ap[1];
            u64 a[8];
            a[0] = pack2(af0.x, af0.x); a[1] = pack2(af0.y, af0.y);
            a[2] = pack2(af0.z, af0.z); a[3] = pack2(af0.w, af0.w);
            a[4] = pack2(af1.x, af1.x); a[5] = pack2(af1.y, af1.y);
            a[6] = pack2(af1.z, af1.z); a[7] = pack2(af1.w, af1.w);
            u64 b[4];
            {
                const ulonglong2* p = reinterpret_cast<const ulonglong2*>(&Bs[cur][k][tx * 8]);
                ulonglong2 w0 = p[0], w1 = p[1];
                b[0]=w0.x; b[1]=w0.y; b[2]=w1.x; b[3]=w1.y;
            }
            #pragma unroll
            for (int i = 0; i < 8; i++)
                #pragma unroll
                for (int j = 0; j < 4; j++)
                    fma2(acc[i][j], a[i], b[j]);
        }
        if (has_nxt) {
            As[nxt][ac0+0][ar] = pa0.x;
            As[nxt][ac0+1][ar] = pa0.y;
            As[nxt][ac0+2][ar] = pa0.z;
            As[nxt][ac0+3][ar] = pa0.w;
            As[nxt][ac0+4][ar] = pa1.x;
            As[nxt][ac0+5][ar] = pa1.y;
            As[nxt][ac0+6][ar] = pa1.z;
            As[nxt][ac0+7][ar] = pa1.w;
            *reinterpret_cast<float4*>(&Bs[nxt][bbr][bbc])     = pb0;
            *reinterpret_cast<float4*>(&Bs[nxt][bbr][bbc + 4]) = pb1;
            __syncthreads();
        }
    }
    #pragma unroll
    for (int i = 0; i < 8; i++) {
        int gr = row0 + ty * 8 + i;
        if (gr >= NN) continue;
        #pragma unroll
        for (int j = 0; j < 4; j++) {
            int gc = col0 + tx * 8 + j * 2;
            if (gc < QKVW) {
                float2 f = unpack2(acc[i][j]);
                if (gc < 640) {
                    int blk = (gc < 320) ? 0 : 320;
                    int c = gc - blk;
                    int h = c >> 4, d = c & 15;
                    int oc = blk + ((d >> 2) * 20 + h) * 4 + (d & 3);  // pair-preserving (d even)
                    __half2 hv = __floats2half2_rn(f.x, f.y);
                    *reinterpret_cast<__half2*>(&g_qkh[(ll)gr * 640 + oc]) = hv;
                } else {
                    *reinterpret_cast<float2*>(&g_v[(ll)gr * DIM + (gc - 640)]) = f;
                }
            }
        }
    }
}

// ---------------- update SGEMM (double-buffered, plain-A smem): G = [xi|mi] @ uw ----------------
__global__ __launch_bounds__(256, 2) void sgemm_upd_kernel(const float* __restrict__ B)
{
    __shared__ float As[2][16][128];
    __shared__ float Bs[2][16][128];
    int tid = threadIdx.x;
    int tx = tid & 15, ty = tid >> 4;
    int row0 = blockIdx.y * 128;
    int col0 = blockIdx.x * 128;
    u64 acc[8][4];
    #pragma unroll
    for (int i = 0; i < 8; i++)
        #pragma unroll
        for (int j = 0; j < 4; j++) acc[i][j] = 0ull;

    const int ar = tid >> 1;
    const int ac0 = (tid & 1) * 8;
    const int agrow = row0 + ar;
    const int bbr = tid >> 4;
    const int bbc = (tid & 15) * 8;
    const int bgcol = col0 + bbc;

    float4 pa0, pa1, pb0, pb1;
    {
        pa0 = make_float4(0,0,0,0); pa1 = make_float4(0,0,0,0);
        if (agrow < NN) {
            const float* s = g_xi + (ll)agrow * DIM + ac0;
            pa0 = *reinterpret_cast<const float4*>(s);
            pa1 = *reinterpret_cast<const float4*>(s + 4);
        }
        pb0 = make_float4(0,0,0,0); pb1 = make_float4(0,0,0,0);
        if (bgcol < DIM) {
            const float* s = B + (ll)bbr * DIM + bgcol;
            pb0 = *reinterpret_cast<const float4*>(s);
            pb1 = *reinterpret_cast<const float4*>(s + 4);
        }
        As[0][ac0+0][ar] = pa0.x;
        As[0][ac0+1][ar] = pa0.y;
        As[0][ac0+2][ar] = pa0.z;
        As[0][ac0+3][ar] = pa0.w;
        As[0][ac0+4][ar] = pa1.x;
        As[0][ac0+5][ar] = pa1.y;
        As[0][ac0+6][ar] = pa1.z;
        As[0][ac0+7][ar] = pa1.w;
        *reinterpret_cast<float4*>(&Bs[0][bbr][bbc])     = pb0;
        *reinterpret_cast<float4*>(&Bs[0][bbr][bbc + 4]) = pb1;
    }
    __syncthreads();

    for (int kt = 0; kt < 22; ++kt) {
        int cur = kt & 1, nxt = cur ^ 1;
        bool has_nxt = (kt + 1 < 22);
        if (has_nxt) {
            int gkbase = (kt + 1) * 16;
            const float* Ap = (gkbase < DIM) ? g_xi : g_mi;
            int koff = (gkbase < DIM) ? gkbase : gkbase - DIM;
            pa0 = make_float4(0,0,0,0); pa1 = make_float4(0,0,0,0);
            if (agrow < NN) {
                const float* s = Ap + (ll)agrow * DIM + koff + ac0;
                pa0 = *reinterpret_cast<const float4*>(s);
                pa1 = *reinterpret_cast<const float4*>(s + 4);
            }
            int gk = gkbase + bbr;
            pb0 = make_float4(0,0,0,0); pb1 = make_float4(0,0,0,0);
            if (bgcol < DIM) {
                const float* s = B + (ll)gk * DIM + bgcol;
                pb0 = *reinterpret_cast<const float4*>(s);
                pb1 = *reinterpret_cast<const float4*>(s + 4);
            }
        }
        #pragma unroll
        for (int k = 0; k < 16; ++k) {
            const float4* ap = reinterpret_cast<const float4*>(&As[cur][k][ty * 8]);
            float4 af0 = ap[0], af1 = ap[1];
            u64 a[8];
            a[0] = pack2(af0.x, af0.x); a[1] = pack2(af0.y, af0.y);
            a[2] = pack2(af0.z, af0.z); a[3] = pack2(af0.w, af0.w);
            a[4] = pack2(af1.x, af1.x); a[5] = pack2(af1.y, af1.y);
            a[6] = pack2(af1.z, af1.z); a[7] = pack2(af1.w, af1.w);
            u64 b[4];
            {
                const ulonglong2* p = reinterpret_cast<const ulonglong2*>(&Bs[cur][k][tx * 8]);
                ulonglong2 w0 = p[0], w1 = p[1];
                b[0]=w0.x; b[1]=w0.y; b[2]=w1.x; b[3]=w1.y;
            }
            #pragma unroll
            for (int i = 0; i < 8; i++)
                #pragma unroll
                for (int j = 0; j < 4; j++)
                    fma2(acc[i][j], a[i], b[j]);
        }
        if (has_nxt) {
            As[nxt][ac0+0][ar] = pa0.x;
            As[nxt][ac0+1][ar] = pa0.y;
            As[nxt][ac0+2][ar] = pa0.z;
            As[nxt][ac0+3][ar] = pa0.w;
            As[nxt][ac0+4][ar] = pa1.x;
            As[nxt][ac0+5][ar] = pa1.y;
            As[nxt][ac0+6][ar] = pa1.z;
            As[nxt][ac0+7][ar] = pa1.w;
            *reinterpret_cast<float4*>(&Bs[nxt][bbr][bbc])     = pb0;
            *reinterpret_cast<float4*>(&Bs[nxt][bbr][bbc + 4]) = pb1;
            __syncthreads();
        }
    }
    #pragma unroll
    for (int i = 0; i < 8; i++) {
        int gr = row0 + ty * 8 + i;
        if (gr >= NN) continue;
        #pragma unroll
        for (int j = 0; j < 4; j++) {
            int gc = col0 + tx * 8 + j * 2;
            if (gc < DIM) {
                float2 f = unpack2(acc[i][j]);
                *reinterpret_cast<float2*>(&g_G[(ll)gr * DIM + gc]) = f;
            }
        }
    }
}

// ---------------- slim edge attention + scatter (fp16 q/k, grid-stride warp-per-edge) ----------------
template<int LAYER>
__global__ __launch_bounds__(256) void edge_attn_kernel(
    const int* __restrict__ src, const int* __restrict__ dst)
{
    __shared__ float s_a[8][20];

    int tid = threadIdx.x;
    int wid = tid >> 5, lane = tid & 31;
    int b0a = 4 * lane;
    int b0b = 4 * (lane + 32);
    int hA0 =  b0a      / VD, hA1 = (b0a + 1) / VD, hA2 = (b0a + 2) / VD, hA3 = (b0a + 3) / VD;
    int hB0 =  b0b      / VD, hB1 = (b0b + 1) / VD, hB2 = (b0b + 2) / VD, hB3 = (b0b + 3) / VD;

    for (int e = blockIdx.x * 8 + wid; e < EE; e += gridDim.x * 8) {
        int is = src[e], id = dst[e];
        float4 y4;
        if (LAYER == 0 && lane < 16)
            y4 = __ldg(reinterpret_cast<const float4*>(g_Y) + e * 4 + (lane & 3));
        const uint2* qh = reinterpret_cast<const uint2*>(g_qkh + (ll)id * 640);
        const uint2* kh = reinterpret_cast<const uint2*>(g_qkh + (ll)is * 640 + 320);
        const float4* wp = reinterpret_cast<const float4*>(g_w + (ll)e * 16);
        // hoist v loads (independent of s_a) — overlap L2 latency with logit FMAs
        const float* vr = g_v + (ll)is * DIM;
        float4 v4a = *reinterpret_cast<const float4*>(vr + b0a);
        float4 v4b = make_float4(0, 0, 0, 0);
        if (lane < 12) v4b = *reinterpret_cast<const float4*>(vr + b0b);
        if (lane < 20) {
            float a0 = 0.f, a1 = 0.f;
            #pragma unroll
            for (int d4 = 0; d4 < 4; d4++) {
                uint2 qu = __ldg(qh + d4 * 20 + lane);
                uint2 ku = __ldg(kh + d4 * 20 + lane);
                float4 w4 = __ldg(wp + d4);
                float2 fqa = __half22float2(*reinterpret_cast<__half2*>(&qu.x));
                float2 fqb = __half22float2(*reinterpret_cast<__half2*>(&qu.y));
                float2 fka = __half22float2(*reinterpret_cast<__half2*>(&ku.x));
                float2 fkb = __half22float2(*reinterpret_cast<__half2*>(&ku.y));
                a0 += fqa.x * fka.x * w4.x + fqa.y * fka.y * w4.y;
                a1 += fqb.x * fkb.x * w4.z + fqb.y * fkb.y * w4.w;
            }
            s_a[wid][lane] = a0 + a1;
        }
        __syncwarp();
        float* mr = &g_mi[(ll)id * DIM];
        {
            float4 o;
            o.x = s_a[wid][hA0] * v4a.x;
            o.y = s_a[wid][hA1] * v4a.y;
            o.z = s_a[wid][hA2] * v4a.z;
            o.w = s_a[wid][hA3] * v4a.w;
            atomicAdd(reinterpret_cast<float4*>(mr + b0a), o);
        }
        if (lane < 12) {
            float4 o;
            o.x = s_a[wid][hB0] * v4b.x;
            o.y = s_a[wid][hB1] * v4b.y;
            o.z = s_a[wid][hB2] * v4b.z;
            o.w = s_a[wid][hB3] * v4b.w;
            atomicAdd(reinterpret_cast<float4*>(mr + b0b), o);
        }
        if (LAYER == 0) {
            if (lane < 16) {
                float at = s_a[wid][16 + (lane >> 2)];
                float4 o = make_float4(at * y4.x, at * y4.y, at * y4.z, at * y4.w);
                atomicAdd(reinterpret_cast<float4*>(&g_Vi[(ll)id * 64 + 4 * lane]), o);
            }
        }
        __syncwarp();
    }
}

// ---------------- residual + LayerNorm (+ zero mi for next layer) ----------------
__global__ void resln_kernel(const float* __restrict__ ub, float* __restrict__ out, int toXi) {
    __shared__ float red[8];
    int n = blockIdx.x, t = threadIdx.x;
    float val = 0.f;
    if (t < DIM) val = g_xi[n * DIM + t] + g_G[n * DIM + t] + ub[t];
    float mu = block_sum_192(val, red) * (1.f / DIM);
    float dx = (t < DIM) ? (val - mu) : 0.f;
    float var = block_sum_192(dx * dx, red) * (1.f / DIM);
    if (t < DIM) {
        float o = dx * rsqrtf(var + 1e-6f);
        if (toXi) {
            g_xi[n * DIM + t] = o;
            g_mi[(ll)n * DIM + t] = 0.f;
        } else {
            out[n * DIM + t] = o;
        }
    }
}

// ---------------- launch ----------------
extern "C" void kernel_launch(void* const* d_in, const int* in_sizes, int n_in,
                              void* d_out, int out_size) {
    const int*   species  = (const int*)  d_in[0];
    const float* dist     = (const float*)d_in[1];
    const float* swtch    = (const float*)d_in[2];
    const int*   esrc     = (const int*)  d_in[3];
    const int*   edst     = (const int*)  d_in[4];
    const float* vec      = (const float*)d_in[5];
    const float* z_table  = (const float*)d_in[6];
    const float* w_sp     = (const float*)d_in[7];
    const float* pw1_0    = (const float*)d_in[8];
    const float* pb1_0    = (const float*)d_in[9];
    const float* pw2_0    = (const float*)d_in[10];
    const float* pb2_0    = (const float*)d_in[11];
    const float* wq_0     = (const float*)d_in[12];
    const float* wk_0     = (const float*)d_in[13];
    const float* wv_0     = (const float*)d_in[14];
    const float* uw_0     = (const float*)d_in[15];
    const float* ub_0     = (const float*)d_in[16];
    const float* pw1_1    = (const float*)d_in[17];
    const float* pb1_1    = (const float*)d_in[18];
    const float* pw2_1    = (const float*)d_in[19];
    const float* pb2_1    = (const float*)d_in[20];
    const float* wq_1     = (const float*)d_in[21];
    const float* wk_1     = (const float*)d_in[22];
    const float* wv_1     = (const float*)d_in[23];
    const float* uw_1     = (const float*)d_in[24];
    const float* ub_1     = (const float*)d_in[25];
    float* out = (float*)d_out;

    const int EB  = (EE + 255) / 256;
    const int EWB = 1184;
    dim3 grid_qkv(7, 79);
    dim3 grid_upd(2, 79);

    node_embed_kernel<<<NN, 192>>>(species, z_table, w_sp);                            // 0
    edge_geom_kernel<<<EB, 256>>>(dist, vec, swtch, pw1_0, pb1_0, pw2_0, pb2_0);       // 1

    // ---- layer 0 ----
    sgemm_qkv_kernel<<<grid_qkv, 256>>>(wq_0, wk_0, wv_0);                             // 2
    edge_attn_kernel<0><<<EWB, 256>>>(esrc, edst);                                     // 3 (profiled)
    sgemm_upd_kernel<<<grid_upd, 256>>>(uw_0);                                         // 4
    resln_kernel<<<NN, 192>>>(ub_0, out, 1);                                           // 5

    // ---- layer 1 ----
    ur1mlp1_kernel<<<EB, 256>>>(esrc, edst, dist, swtch, pw1_1, pb1_1, pw2_1, pb2_1);  // 6
    sgemm_qkv_kernel<<<grid_qkv, 256>>>(wq_1, wk_1, wv_1);                             // 7
    edge_attn_kernel<1><<<EWB, 256>>>(esrc, edst);                                     // 8
    sgemm_upd_kernel<<<grid_upd, 256>>>(uw_1);                                         // 9
    resln_kernel<<<NN, 192>>>(ub_1, out, 0);                                           // 10
}